// round 12
// baseline (speedup 1.0000x reference)
#include <cuda_runtime.h>
#include <cuda_bf16.h>
#include <cuda_fp16.h>
#include <math.h>
#include <stdint.h>

// Problem dims (compile-time)
#define E_  768
#define H_  12
#define D_  64
#define L_  4
#define S_  1024
#define B_  2
#define V_  32000
#define FF_ 4608
#define M_  (B_ * S_)   // 2048 rows
#define QKVN 2304       // 3*E

// ---------------- scratch ----------------
__device__ float g_x[M_ * E_];                       // residual stream (fp32)
__device__ float g_bqkv[L_ * QKVN];                  // concatenated qkv bias
__device__ __nv_bfloat16 g_qkvh[(size_t)M_ * QKVN];  // qkv hi plane (bf16, for flash)
__device__ __nv_bfloat16 g_qkvl[(size_t)M_ * QKVN];  // qkv lo plane
// activation split planes (fp16)
__device__ __half g_ahE[(size_t)M_ * E_];
__device__ __half g_alE[(size_t)M_ * E_];
__device__ __half g_ahF[(size_t)M_ * FF_];
__device__ __half g_alF[(size_t)M_ * FF_];
// weights: single fp16 plane
__device__ __half g_wqkv[(size_t)L_ * E_ * QKVN];
__device__ __half g_wo  [(size_t)L_ * E_ * E_];
__device__ __half g_w1  [(size_t)L_ * E_ * FF_];
__device__ __half g_w2  [(size_t)L_ * FF_ * E_];
__device__ __half g_wf  [(size_t)E_ * V_];

// ---------------- small helpers ----------------
__device__ __forceinline__ uint32_t pack_bf2(float a, float b) {
    __nv_bfloat162 t = __floats2bfloat162_rn(a, b);
    return *reinterpret_cast<uint32_t*>(&t);
}
__device__ __forceinline__ void split_write2_bf(float v0, float v1,
                                                __nv_bfloat16* ph, __nv_bfloat16* pl) {
    __nv_bfloat16 h0 = __float2bfloat16(v0), h1 = __float2bfloat16(v1);
    __nv_bfloat162 hh; hh.x = h0; hh.y = h1;
    *(__nv_bfloat162*)ph = hh;
    __nv_bfloat162 ll;
    ll.x = __float2bfloat16(v0 - __bfloat162float(h0));
    ll.y = __float2bfloat16(v1 - __bfloat162float(h1));
    *(__nv_bfloat162*)pl = ll;
}
__device__ __forceinline__ void split_write2_h(float v0, float v1,
                                               __half* ph, __half* pl) {
    __half h0 = __float2half_rn(v0), h1 = __float2half_rn(v1);
    *(__half2*)ph = __halves2half2(h0, h1);
    *(__half2*)pl = __halves2half2(__float2half_rn(v0 - __half2float(h0)),
                                   __float2half_rn(v1 - __half2float(h1)));
}
__device__ __forceinline__ void split_pack2_bf(float a, float b, uint32_t& hi, uint32_t& lo) {
    __nv_bfloat16 ha = __float2bfloat16(a), hb = __float2bfloat16(b);
    __nv_bfloat162 hh; hh.x = ha; hh.y = hb;
    hi = *reinterpret_cast<uint32_t*>(&hh);
    lo = pack_bf2(a - __bfloat162float(ha), b - __bfloat162float(hb));
}

// ---------------- embedding ----------------
__global__ void embed_kernel(const int* __restrict__ tokens,
                             const float* __restrict__ tok_emb,
                             const float* __restrict__ pos_emb,
                             float* __restrict__ x)
{
    int row = blockIdx.x;
    int s   = row % S_;
    int t   = tokens[row];
    const float4* te = (const float4*)(tok_emb + (size_t)t * E_);
    const float4* pe = (const float4*)(pos_emb + (size_t)s * E_);
    float4*       xo = (float4*)(x + (size_t)row * E_);
    for (int i = threadIdx.x; i < E_ / 4; i += blockDim.x) {
        float4 a = te[i], b = pe[i];
        xo[i] = make_float4(a.x + b.x, a.y + b.y, a.z + b.z, a.w + b.w);
    }
}

// ---------------- layernorm -> fp16 split planes (single-pass, register-resident) ----------------
__global__ void __launch_bounds__(256)
ln_split_kernel(const float* __restrict__ x,
                const float* __restrict__ g,
                const float* __restrict__ b,
                __half* __restrict__ oh,
                __half* __restrict__ ol)
{
    int row = blockIdx.x;
    int tid = threadIdx.x;
    __shared__ float red[256];
    const float4* xr4 = (const float4*)(x + (size_t)row * E_);

    float4 v = make_float4(0.f, 0.f, 0.f, 0.f);
    bool act = tid < E_ / 4;          // 192 active
    if (act) v = xr4[tid];

    float s = v.x + v.y + v.z + v.w;
    red[tid] = s; __syncthreads();
    for (int o = 128; o > 0; o >>= 1) { if (tid < o) red[tid] += red[tid + o]; __syncthreads(); }
    float mean = red[0] * (1.f / E_);
    __syncthreads();

    float sq = 0.f;
    if (act) {
        float d0 = v.x - mean, d1 = v.y - mean, d2 = v.z - mean, d3 = v.w - mean;
        sq = d0 * d0 + d1 * d1 + d2 * d2 + d3 * d3;
    }
    red[tid] = sq; __syncthreads();
    for (int o = 128; o > 0; o >>= 1) { if (tid < o) red[tid] += red[tid + o]; __syncthreads(); }
    float inv = rsqrtf(red[0] * (1.f / E_) + 1e-5f);

    if (act) {
        float4 g4 = ((const float4*)g)[tid];
        float4 b4 = ((const float4*)b)[tid];
        float y0 = (v.x - mean) * inv * g4.x + b4.x;
        float y1 = (v.y - mean) * inv * g4.y + b4.y;
        float y2 = (v.z - mean) * inv * g4.z + b4.z;
        float y3 = (v.w - mean) * inv * g4.w + b4.w;
        int col = tid * 4;
        __half* ohr = oh + (size_t)row * E_ + col;
        __half* olr = ol + (size_t)row * E_ + col;
        split_write2_h(y0, y1, ohr,     olr);
        split_write2_h(y2, y3, ohr + 2, olr + 2);
    }
}

// ---------------- fused weight conversion: all tensors, one launch ----------------
#define CS0 (L_ * E_ * E_ / 4)      // per tensor: Wq / Wk / Wv / Wo
#define CS1 (L_ * E_ * FF_ / 4)     // W1 / W2
#define CS2 (E_ * V_ / 4)           // Wf
#define CTOTAL (4 * CS0 + 2 * CS1 + CS2)
__global__ void convert_all_kernel(const float4* __restrict__ Wq4, const float4* __restrict__ Wk4,
                                   const float4* __restrict__ Wv4, const float4* __restrict__ Wo4,
                                   const float4* __restrict__ W14, const float4* __restrict__ W24,
                                   const float4* __restrict__ Wf4,
                                   uint2* __restrict__ wqkv_u, uint2* __restrict__ wo_u,
                                   uint2* __restrict__ w1_u, uint2* __restrict__ w2_u,
                                   uint2* __restrict__ wf_u)
{
    for (int idx = blockIdx.x * blockDim.x + threadIdx.x; idx < CTOTAL;
         idx += gridDim.x * blockDim.x) {
        float4 w;
        uint2* dst;
        if (idx < 3 * CS0) {                         // Q|K|V -> interleaved wqkv
            int which = idx / CS0;
            int r = idx - which * CS0;
            const float4* src = (which == 0) ? Wq4 : (which == 1) ? Wk4 : Wv4;
            w = src[r];
            int l  = r / (E_ * E_ / 4);
            int rr = r - l * (E_ * E_ / 4);
            int row = rr / (E_ / 4);
            int n4  = rr - row * (E_ / 4);
            dst = wqkv_u + ((size_t)l * E_ + row) * (QKVN / 4) + which * (E_ / 4) + n4;
        } else if (idx < 4 * CS0) {                  // Wo linear
            int r = idx - 3 * CS0;
            w = Wo4[r]; dst = wo_u + r;
        } else if (idx < 4 * CS0 + CS1) {            // W1 linear
            int r = idx - 4 * CS0;
            w = W14[r]; dst = w1_u + r;
        } else if (idx < 4 * CS0 + 2 * CS1) {        // W2 linear
            int r = idx - 4 * CS0 - CS1;
            w = W24[r]; dst = w2_u + r;
        } else {                                     // Wf linear
            int r = idx - 4 * CS0 - 2 * CS1;
            w = Wf4[r]; dst = wf_u + r;
        }
        __half2 p0 = __floats2half2_rn(w.x, w.y);
        __half2 p1 = __floats2half2_rn(w.z, w.w);
        uint2 hv;
        hv.x = *reinterpret_cast<uint32_t*>(&p0);
        hv.y = *reinterpret_cast<uint32_t*>(&p1);
        *dst = hv;
    }
}

__global__ void concat_bias_kernel(const float* __restrict__ bq,
                                   const float* __restrict__ bk,
                                   const float* __restrict__ bv,
                                   float* __restrict__ bqkv)
{
    int t = blockIdx.x * blockDim.x + threadIdx.x;
    if (t >= L_ * QKVN) return;
    int l = t / QKVN, c = t - l * QKVN;
    float v;
    if (c < E_)           v = bq[l * E_ + c];
    else if (c < 2 * E_)  v = bk[l * E_ + c - E_];
    else                  v = bv[l * E_ + c - 2 * E_];
    bqkv[t] = v;
}

// ---------------- PTX helpers ----------------
__device__ __forceinline__ void cp_async16(uint32_t s, const void* g) {
    asm volatile("cp.async.cg.shared.global [%0], [%1], 16;" :: "r"(s), "l"(g));
}
__device__ __forceinline__ void cp_commit() {
    asm volatile("cp.async.commit_group;");
}
template<int N>
__device__ __forceinline__ void cp_wait() {
    asm volatile("cp.async.wait_group %0;" :: "n"(N));
}
__device__ __forceinline__ void ldm_x4(uint32_t* r, uint32_t addr) {
    asm volatile("ldmatrix.sync.aligned.m8n8.x4.shared.b16 {%0,%1,%2,%3}, [%4];"
                 : "=r"(r[0]), "=r"(r[1]), "=r"(r[2]), "=r"(r[3]) : "r"(addr));
}
__device__ __forceinline__ void ldm_x4_trans(uint32_t* r, uint32_t addr) {
    asm volatile("ldmatrix.sync.aligned.m8n8.x4.trans.shared.b16 {%0,%1,%2,%3}, [%4];"
                 : "=r"(r[0]), "=r"(r[1]), "=r"(r[2]), "=r"(r[3]) : "r"(addr));
}
__device__ __forceinline__ void mma_bf16(float* d, const uint32_t* a, const uint32_t* b) {
    asm volatile(
        "mma.sync.aligned.m16n8k16.row.col.f32.bf16.bf16.f32 "
        "{%0,%1,%2,%3}, {%4,%5,%6,%7}, {%8,%9}, {%0,%1,%2,%3};"
        : "+f"(d[0]), "+f"(d[1]), "+f"(d[2]), "+f"(d[3])
        : "r"(a[0]), "r"(a[1]), "r"(a[2]), "r"(a[3]), "r"(b[0]), "r"(b[1]));
}
__device__ __forceinline__ void mma_f16(float* d, const uint32_t* a, const uint32_t* b) {
    asm volatile(
        "mma.sync.aligned.m16n8k16.row.col.f32.f16.f16.f32 "
        "{%0,%1,%2,%3}, {%4,%5,%6,%7}, {%8,%9}, {%0,%1,%2,%3};"
        : "+f"(d[0]), "+f"(d[1]), "+f"(d[2]), "+f"(d[3])
        : "r"(a[0]), "r"(a[1]), "r"(a[2]), "r"(a[3]), "r"(b[0]), "r"(b[1]));
}

// ---------------- fp16 2-term tensor-core GEMM, 4-stage cp.async pipeline ----------------
// C[M,N] = Ah@Bf + Al@Bf  (A exact as fp16 pair, B single-rounded fp16).
// MI: 2 -> BM=128; 1 -> BM=64 (for N=768 GEMMs, fills 148 SMs with 192 blocks).
// OUT: 0 = fp32 C (bias/res), 2 = bf16 split planes, 3 = fp16 split planes
#define GLDA 40
#define GLDB 136
#define GSTAGES 4
#define GABYTES(MI) ((MI) * 64 * GLDA * 2)
#define GBBYTES (32 * GLDB * 2)
#define GSMEM(MI) (GSTAGES * (GABYTES(MI) + GBBYTES))   // MI=2: 75776, MI=1: 55296
template<int MI, int OUT, bool BIAS, bool RES, bool GELU>
__global__ void __launch_bounds__(256)
bgemm2_kernel(const __half* __restrict__ Ah, const __half* __restrict__ Al,
              const __half* __restrict__ Bf,
              const float* __restrict__ bias, const float* __restrict__ res,
              float* __restrict__ Cf,
              __nv_bfloat16* __restrict__ Cbh, __nv_bfloat16* __restrict__ Cbl,
              __half* __restrict__ Chh, __half* __restrict__ Chl,
              int Nd, int Kd)
{
    extern __shared__ __half dsm[];

    int tid  = threadIdx.x;
    int lane = tid & 31, wid = tid >> 5;
    int wm = wid & 3, wn = wid >> 2;
    int row0 = blockIdx.x * (MI * 64), col0 = blockIdx.y * 128;

    uint32_t as0 = (uint32_t)__cvta_generic_to_shared(dsm);
    uint32_t bs0 = as0 + GSTAGES * GABYTES(MI);

    float acc[MI][8][4];
    #pragma unroll
    for (int i = 0; i < MI; ++i)
        #pragma unroll
        for (int j = 0; j < 8; ++j)
            #pragma unroll
            for (int t = 0; t < 4; ++t) acc[i][j][t] = 0.f;

    const int KSEG = Kd / 32;
    const int KT   = 2 * KSEG;

    auto load_tile = [&](int buf, int kt) {
        int seg = (kt < KSEG) ? 0 : 1;
        const __half* Ab = seg ? Al : Ah;
        int k0 = (kt - seg * KSEG) * 32;
        uint32_t ab = as0 + buf * GABYTES(MI);
        uint32_t bb = bs0 + buf * GBBYTES;
        #pragma unroll
        for (int i = 0; i < MI; ++i) {
            int chunk = tid * MI + i;
            int m = chunk >> 2, c = chunk & 3;
            const void* g = Ab + (size_t)(row0 + m) * Kd + k0 + c * 8;
            cp_async16(ab + (uint32_t)(m * GLDA + c * 8) * 2, g);
        }
        #pragma unroll
        for (int i = 0; i < 2; ++i) {
            int chunk = tid * 2 + i;
            int k = chunk >> 4, c = chunk & 15;
            const void* g = Bf + (size_t)(k0 + k) * Nd + col0 + c * 8;
            cp_async16(bb + (uint32_t)(k * GLDB + c * 8) * 2, g);
        }
    };

    #pragma unroll
    for (int p = 0; p < GSTAGES - 1; ++p) {
        if (p < KT) load_tile(p, p);
        cp_commit();
    }

    for (int kt = 0; kt < KT; ++kt) {
        cp_wait<GSTAGES - 2>();
        __syncthreads();
        int buf = kt & (GSTAGES - 1);
        uint32_t ab = as0 + buf * GABYTES(MI);
        uint32_t bb = bs0 + buf * GBBYTES;

        #pragma unroll
        for (int kk = 0; kk < 2; ++kk) {
            uint32_t af[MI][4];
            #pragma unroll
            for (int mi = 0; mi < MI; ++mi) {
                int m  = wm * (16 * MI) + mi * 16 + (lane & 15);
                int kc = kk * 16 + (lane >> 4) * 8;
                ldm_x4(af[mi], ab + (uint32_t)(m * GLDA + kc) * 2);
            }
            uint32_t bfrag[8][2];
            #pragma unroll
            for (int ni4 = 0; ni4 < 4; ++ni4) {
                int g    = lane >> 3;
                int krow = kk * 16 + (g & 1) * 8 + (lane & 7);
                int ncol = wn * 64 + ni4 * 16 + (g >> 1) * 8;
                uint32_t r[4];
                ldm_x4_trans(r, bb + (uint32_t)(krow * GLDB + ncol) * 2);
                bfrag[2 * ni4][0] = r[0]; bfrag[2 * ni4][1] = r[1];
                bfrag[2 * ni4 + 1][0] = r[2]; bfrag[2 * ni4 + 1][1] = r[3];
            }
            #pragma unroll
            for (int mi = 0; mi < MI; ++mi)
                #pragma unroll
                for (int ni = 0; ni < 8; ++ni)
                    mma_f16(acc[mi][ni], af[mi], bfrag[ni]);
        }

        int nx = kt + GSTAGES - 1;
        if (nx < KT) load_tile(nx & (GSTAGES - 1), nx);
        cp_commit();
    }

    // epilogue
    #pragma unroll
    for (int mi = 0; mi < MI; ++mi) {
        int r = row0 + wm * (16 * MI) + mi * 16 + (lane >> 2);
        #pragma unroll
        for (int ni = 0; ni < 8; ++ni) {
            int c = col0 + wn * 64 + ni * 8 + (lane & 3) * 2;
            float b0 = 0.f, b1 = 0.f;
            if (BIAS) { b0 = bias[c]; b1 = bias[c + 1]; }
            #pragma unroll
            for (int half = 0; half < 2; ++half) {
                int rr = r + half * 8;
                float v0 = acc[mi][ni][half * 2 + 0] + b0;
                float v1 = acc[mi][ni][half * 2 + 1] + b1;
                if (GELU) {
                    v0 = 0.5f * v0 * (1.f + erff(v0 * 0.70710678118654752f));
                    v1 = 0.5f * v1 * (1.f + erff(v1 * 0.70710678118654752f));
                }
                if (RES) {
                    const float2 rv = *(const float2*)(res + (size_t)rr * Nd + c);
                    v0 += rv.x; v1 += rv.y;
                }
                if (OUT == 0) {
                    *(float2*)(Cf + (size_t)rr * Nd + c) = make_float2(v0, v1);
                } else if (OUT == 2) {
                    split_write2_bf(v0, v1, Cbh + (size_t)rr * Nd + c, Cbl + (size_t)rr * Nd + c);
                } else {
                    split_write2_h(v0, v1, Chh + (size_t)rr * Nd + c, Chl + (size_t)rr * Nd + c);
                }
            }
        }
    }
}

// ---------------- flash attention (split-3 bf16, 128-row Q tiles, 256 threads) ----------------
// qkvh/qkvl: [M, 2304] bf16 split planes (q|k|v each 768 = 12 heads x 64).
// S = Qh Kh^T + Qh Kl^T + Ql Kh^T; O += Ph Vh + Ph Vl + Pl Vh.
// 8 warps, each owns 16 Q rows; K/V tiles of 64 rows serve all 128 Q rows.
#define LDQ 72
#define FA_KTILE (64 * LDQ)
#define FA_QTILE (128 * LDQ)
#define FA_SMEM ((2 * FA_QTILE + 4 * FA_KTILE) * 2)   // 73728 B
__global__ void __launch_bounds__(256)
flash_kernel(const __nv_bfloat16* __restrict__ qkvh,
             const __nv_bfloat16* __restrict__ qkvl,
             __half* __restrict__ oh, __half* __restrict__ ol)
{
    extern __shared__ __nv_bfloat16 smem[];
    __nv_bfloat16* Qh = smem;
    __nv_bfloat16* Ql = Qh + FA_QTILE;
    __nv_bfloat16* Kh = Ql + FA_QTILE;
    __nv_bfloat16* Kl = Kh + FA_KTILE;
    __nv_bfloat16* Vh = Kl + FA_KTILE;
    __nv_bfloat16* Vl = Vh + FA_KTILE;

    int it = (S_ / 128 - 1) - blockIdx.x;   // zigzag: heaviest tiles first
    int z  = blockIdx.y;
    int b = z / H_, h = z % H_;
    int tid = threadIdx.x, lane = tid & 31, wm = tid >> 5;   // wm 0..7
    size_t rowbase = (size_t)b * S_;

    // load Q tile (128 rows, hi + lo)
    {
        size_t qoff = (rowbase + it * 128) * QKVN + h * D_;
        for (int cc = tid; cc < 1024; cc += 256) {
            int r = cc >> 3, c = cc & 7;
            *(uint4*)&Qh[r * LDQ + c * 8] = *(const uint4*)(qkvh + qoff + (size_t)r * QKVN + c * 8);
            *(uint4*)&Ql[r * LDQ + c * 8] = *(const uint4*)(qkvl + qoff + (size_t)r * QKVN + c * 8);
        }
    }
    uint32_t qh_s = (uint32_t)__cvta_generic_to_shared(Qh);
    uint32_t ql_s = (uint32_t)__cvta_generic_to_shared(Ql);
    uint32_t kh_s = (uint32_t)__cvta_generic_to_shared(Kh);
    uint32_t kl_s = (uint32_t)__cvta_generic_to_shared(Kl);
    uint32_t vh_s = (uint32_t)__cvta_generic_to_shared(Vh);
    uint32_t vl_s = (uint32_t)__cvta_generic_to_shared(Vl);

    float oacc[8][4];
    #pragma unroll
    for (int j = 0; j < 8; ++j)
        #pragma unroll
        for (int t = 0; t < 4; ++t) oacc[j][t] = 0.f;
    float m_prev[2] = { -1e30f, -1e30f };
    float lsum[2]   = { 0.f, 0.f };

    int jt_max = 2 * it + 1;
    for (int jt = 0; jt <= jt_max; ++jt) {
        __syncthreads();
        size_t koff = (rowbase + jt * 64) * QKVN + E_ + h * D_;
        size_t voff = koff + E_;
        for (int cc = tid; cc < 512; cc += 256) {
            int r = cc >> 3, c = cc & 7;
            size_t gr = (size_t)r * QKVN + c * 8;
            int so = r * LDQ + c * 8;
            *(uint4*)&Kh[so] = *(const uint4*)(qkvh + koff + gr);
            *(uint4*)&Kl[so] = *(const uint4*)(qkvl + koff + gr);
            *(uint4*)&Vh[so] = *(const uint4*)(qkvh + voff + gr);
            *(uint4*)&Vl[so] = *(const uint4*)(qkvl + voff + gr);
        }
        __syncthreads();

        // S = Qh Kh + Qh Kl + Ql Kh  (warp's 16 rows x 64 cols)
        float sacc[8][4];
        #pragma unroll
        for (int j = 0; j < 8; ++j)
            #pragma unroll
            for (int t = 0; t < 4; ++t) sacc[j][t] = 0.f;

        #pragma unroll
        for (int kc = 0; kc < 4; ++kc) {
            uint32_t a_off = (uint32_t)((wm * 16 + (lane & 15)) * LDQ + kc * 16 + (lane >> 4) * 8) * 2;
            uint32_t afh[4], afl[4];
            ldm_x4(afh, qh_s + a_off);
            ldm_x4(afl, ql_s + a_off);
            #pragma unroll
            for (int np = 0; np < 4; ++np) {
                int nrow = np * 16 + (lane & 7) + ((lane >> 4) << 3);
                int ncol = kc * 16 + ((lane >> 3) & 1) * 8;
                uint32_t b_off = (uint32_t)(nrow * LDQ + ncol) * 2;
                uint32_t brh[4], brl[4];
                ldm_x4(brh, kh_s + b_off);
                ldm_x4(brl, kl_s + b_off);
                mma_bf16(sacc[np * 2],     afh, brh);
                mma_bf16(sacc[np * 2],     afh, brl);
                mma_bf16(sacc[np * 2],     afl, brh);
                mma_bf16(sacc[np * 2 + 1], afh, brh + 2);
                mma_bf16(sacc[np * 2 + 1], afh, brl + 2);
                mma_bf16(sacc[np * 2 + 1], afl, brh + 2);
            }
        }

        // scale + causal mask + rowmax
        int rloc = wm * 16 + (lane >> 2);
        float mtile[2] = { -1e30f, -1e30f };
        bool diag = (jt * 64 + 63 > it * 128 + wm * 16);
        #pragma unroll
        for (int j = 0; j < 8; ++j) {
            int cg = jt * 64 + j * 8 + (lane & 3) * 2;
            #pragma unroll
            for (int rh = 0; rh < 2; ++rh) {
                int rg = it * 128 + rloc + rh * 8;
                float s0 = sacc[j][rh * 2]     * 0.125f;
                float s1 = sacc[j][rh * 2 + 1] * 0.125f;
                if (diag) {
                    if (cg     > rg) s0 = -1e30f;
                    if (cg + 1 > rg) s1 = -1e30f;
                }
                sacc[j][rh * 2]     = s0;
                sacc[j][rh * 2 + 1] = s1;
                mtile[rh] = fmaxf(mtile[rh], fmaxf(s0, s1));
            }
        }
        #pragma unroll
        for (int rh = 0; rh < 2; ++rh) {
            mtile[rh] = fmaxf(mtile[rh], __shfl_xor_sync(0xffffffff, mtile[rh], 1));
            mtile[rh] = fmaxf(mtile[rh], __shfl_xor_sync(0xffffffff, mtile[rh], 2));
        }
        float alpha[2];
        #pragma unroll
        for (int rh = 0; rh < 2; ++rh) {
            float mn = fmaxf(m_prev[rh], mtile[rh]);
            alpha[rh] = __expf(m_prev[rh] - mn);
            m_prev[rh] = mn;
        }
        float rsum[2] = { 0.f, 0.f };
        #pragma unroll
        for (int j = 0; j < 8; ++j)
            #pragma unroll
            for (int rh = 0; rh < 2; ++rh) {
                float p0 = __expf(sacc[j][rh * 2]     - m_prev[rh]);
                float p1 = __expf(sacc[j][rh * 2 + 1] - m_prev[rh]);
                sacc[j][rh * 2] = p0; sacc[j][rh * 2 + 1] = p1;
                rsum[rh] += p0 + p1;
            }
        #pragma unroll
        for (int rh = 0; rh < 2; ++rh) {
            rsum[rh] += __shfl_xor_sync(0xffffffff, rsum[rh], 1);
            rsum[rh] += __shfl_xor_sync(0xffffffff, rsum[rh], 2);
            lsum[rh] = lsum[rh] * alpha[rh] + rsum[rh];
        }
        #pragma unroll
        for (int j = 0; j < 8; ++j)
            #pragma unroll
            for (int rh = 0; rh < 2; ++rh) {
                oacc[j][rh * 2]     *= alpha[rh];
                oacc[j][rh * 2 + 1] *= alpha[rh];
            }
        // O += Ph Vh + Ph Vl + Pl Vh
        #pragma unroll
        for (int kc = 0; kc < 4; ++kc) {
            uint32_t pah[4], pal[4];
            split_pack2_bf(sacc[2 * kc][0],     sacc[2 * kc][1],     pah[0], pal[0]);
            split_pack2_bf(sacc[2 * kc][2],     sacc[2 * kc][3],     pah[1], pal[1]);
            split_pack2_bf(sacc[2 * kc + 1][0], sacc[2 * kc + 1][1], pah[2], pal[2]);
            split_pack2_bf(sacc[2 * kc + 1][2], sacc[2 * kc + 1][3], pah[3], pal[3]);
            #pragma unroll
            for (int np = 0; np < 4; ++np) {
                int g = lane >> 3;
                int krow = kc * 16 + (g & 1) * 8 + (lane & 7);
                int ncol = np * 16 + (g >> 1) * 8;
                uint32_t v_off = (uint32_t)(krow * LDQ + ncol) * 2;
                uint32_t brh[4], brl[4];
                ldm_x4_trans(brh, vh_s + v_off);
                ldm_x4_trans(brl, vl_s + v_off);
                mma_bf16(oacc[np * 2],     pah, brh);
                mma_bf16(oacc[np * 2],     pah, brl);
                mma_bf16(oacc[np * 2],     pal, brh);
                mma_bf16(oacc[np * 2 + 1], pah, brh + 2);
                mma_bf16(oacc[np * 2 + 1], pah, brl + 2);
                mma_bf16(oacc[np * 2 + 1], pal, brh + 2);
            }
        }
    }

    // write out (fp16 split planes)
    float inv[2] = { 1.f / lsum[0], 1.f / lsum[1] };
    size_t gr0 = rowbase + it * 128 + wm * 16 + (lane >> 2);
    #pragma unroll
    for (int j = 0; j < 8; ++j) {
        int col = h * D_ + j * 8 + (lane & 3) * 2;
        #pragma unroll
        for (int rh = 0; rh < 2; ++rh) {
            size_t gr = gr0 + rh * 8;
            float v0 = oacc[j][rh * 2]     * inv[rh];
            float v1 = oacc[j][rh * 2 + 1] * inv[rh];
            split_write2_h(v0, v1, oh + gr * E_ + col, ol + gr * E_ + col);
        }
    }
}

// ---------------- host launcher ----------------
extern "C" void kernel_launch(void* const* d_in, const int* in_sizes, int n_in,
                              void* d_out, int out_size)
{
    const int*   tokens  = (const int*)  d_in[0];
    const float* tok_emb = (const float*)d_in[1];
    const float* pos_emb = (const float*)d_in[2];
    const float* Wq = (const float*)d_in[3];
    const float* bq = (const float*)d_in[4];
    const float* Wk = (const float*)d_in[5];
    const float* bk = (const float*)d_in[6];
    const float* Wv = (const float*)d_in[7];
    const float* bv = (const float*)d_in[8];
    const float* Wo = (const float*)d_in[9];
    const float* bo = (const float*)d_in[10];
    const float* ln1_g = (const float*)d_in[11];
    const float* ln1_b = (const float*)d_in[12];
    const float* ln2_g = (const float*)d_in[13];
    const float* ln2_b = (const float*)d_in[14];
    const float* W1 = (const float*)d_in[15];
    const float* b1 = (const float*)d_in[16];
    const float* W2 = (const float*)d_in[17];
    const float* b2 = (const float*)d_in[18];
    const float* lnf_g = (const float*)d_in[19];
    const float* lnf_b = (const float*)d_in[20];
    const float* Wf = (const float*)d_in[21];
    const float* bf = (const float*)d_in[22];
    float* out = (float*)d_out;

    float *x, *bqkv;
    __nv_bfloat16 *qkvh, *qkvl;
    __half *ahE, *alE, *ahF, *alF;
    __half *wqkv, *wo, *w1, *w2, *wf;
    cudaGetSymbolAddress((void**)&x,    g_x);
    cudaGetSymbolAddress((void**)&bqkv, g_bqkv);
    cudaGetSymbolAddress((void**)&qkvh, g_qkvh);
    cudaGetSymbolAddress((void**)&qkvl, g_qkvl);
    cudaGetSymbolAddress((void**)&ahE,  g_ahE);
    cudaGetSymbolAddress((void**)&alE,  g_alE);
    cudaGetSymbolAddress((void**)&ahF,  g_ahF);
    cudaGetSymbolAddress((void**)&alF,  g_alF);
    cudaGetSymbolAddress((void**)&wqkv, g_wqkv);
    cudaGetSymbolAddress((void**)&wo,   g_wo);
    cudaGetSymbolAddress((void**)&w1,   g_w1);
    cudaGetSymbolAddress((void**)&w2,   g_w2);
    cudaGetSymbolAddress((void**)&wf,   g_wf);

    const size_t EE = (size_t)E_ * E_;
    cudaFuncSetAttribute(flash_kernel, cudaFuncAttributeMaxDynamicSharedMemorySize, FA_SMEM);
    cudaFuncSetAttribute(bgemm2_kernel<2, 2, true, false, false>,
                         cudaFuncAttributeMaxDynamicSharedMemorySize, GSMEM(2));
    cudaFuncSetAttribute(bgemm2_kernel<1, 0, true, true, false>,
                         cudaFuncAttributeMaxDynamicSharedMemorySize, GSMEM(1));
    cudaFuncSetAttribute(bgemm2_kernel<2, 3, true, false, true>,
                         cudaFuncAttributeMaxDynamicSharedMemorySize, GSMEM(2));
    cudaFuncSetAttribute(bgemm2_kernel<2, 0, true, false, false>,
                         cudaFuncAttributeMaxDynamicSharedMemorySize, GSMEM(2));

    // ---- fused weight conversion (one launch) ----
    convert_all_kernel<<<4096, 256>>>(
        (const float4*)Wq, (const float4*)Wk, (const float4*)Wv, (const float4*)Wo,
        (const float4*)W1, (const float4*)W2, (const float4*)Wf,
        (uint2*)wqkv, (uint2*)wo, (uint2*)w1, (uint2*)w2, (uint2*)wf);
    concat_bias_kernel<<<(L_ * QKVN + 255) / 256, 256>>>(bq, bk, bv, bqkv);

    embed_kernel<<<M_, 192>>>(tokens, tok_emb, pos_emb, x);

    dim3 gQKV   (M_ / 128, QKVN / 128);   // 16 x 18
    dim3 gProj64(M_ / 64,  E_ / 128);     // 32 x 6 = 192 blocks (fills 148 SMs)
    dim3 gFF1   (M_ / 128, FF_ / 128);    // 16 x 36
    dim3 gHead  (M_ / 128, V_ / 128);     // 16 x 250
    dim3 gFA    (S_ / 128, B_ * H_);      // 8 x 24 = 192 blocks

    for (int l = 0; l < L_; ++l) {
        size_t qoff = (size_t)l * E_ * QKVN;
        size_t ooff = (size_t)l * EE;
        size_t f1 = (size_t)l * E_ * FF_;
        size_t f2 = (size_t)l * FF_ * E_;

        ln_split_kernel<<<M_, 256>>>(x, ln1_g + l * E_, ln1_b + l * E_, ahE, alE);

        // qkv = h @ Wqkv + b   -> bf16 split planes (qkvh, qkvl)
        bgemm2_kernel<2, 2, true, false, false><<<gQKV, 256, GSMEM(2)>>>(
            ahE, alE, wqkv + qoff, bqkv + l * QKVN, nullptr,
            nullptr, qkvh, qkvl, nullptr, nullptr, QKVN, E_);

        // o -> fp16 split planes
        flash_kernel<<<gFA, 256, FA_SMEM>>>(qkvh, qkvl, ahE, alE);

        // x = x + o @ Wo + bo     (BM=64 variant)
        bgemm2_kernel<1, 0, true, true, false><<<gProj64, 256, GSMEM(1)>>>(
            ahE, alE, wo + ooff, bo + l * E_, x,
            x, nullptr, nullptr, nullptr, nullptr, E_, E_);

        ln_split_kernel<<<M_, 256>>>(x, ln2_g + l * E_, ln2_b + l * E_, ahE, alE);

        // ff = gelu(h @ W1 + b1) -> fp16 split planes
        bgemm2_kernel<2, 3, true, false, true><<<gFF1, 256, GSMEM(2)>>>(
            ahE, alE, w1 + f1, b1 + l * FF_, nullptr,
            nullptr, nullptr, nullptr, ahF, alF, FF_, E_);

        // x = x + ff @ W2 + b2    (BM=64 variant)
        bgemm2_kernel<1, 0, true, true, false><<<gProj64, 256, GSMEM(1)>>>(
            ahF, alF, w2 + f2, b2 + l * E_, x,
            x, nullptr, nullptr, nullptr, nullptr, E_, FF_);
    }

    ln_split_kernel<<<M_, 256>>>(x, lnf_g, lnf_b, ahE, alE);
    bgemm2_kernel<2, 0, true, false, false><<<gHead, 256, GSMEM(2)>>>(
        ahE, alE, wf, bf, nullptr,
        out, nullptr, nullptr, nullptr, nullptr, V_, E_);
}

// round 13
// speedup vs baseline: 1.0721x; 1.0721x over previous
#include <cuda_runtime.h>
#include <cuda_bf16.h>
#include <cuda_fp16.h>
#include <math.h>
#include <stdint.h>

// Problem dims (compile-time)
#define E_  768
#define H_  12
#define D_  64
#define L_  4
#define S_  1024
#define B_  2
#define V_  32000
#define FF_ 4608
#define M_  (B_ * S_)   // 2048 rows
#define QKVN 2304       // 3*E

// ---------------- scratch ----------------
__device__ float g_x[M_ * E_];                       // residual stream (fp32)
__device__ float g_bqkv[L_ * QKVN];                  // concatenated qkv bias
__device__ __nv_bfloat16 g_qkvh[(size_t)M_ * QKVN];  // qkv hi plane (bf16, for flash)
__device__ __nv_bfloat16 g_qkvl[(size_t)M_ * QKVN];  // qkv lo plane
// activation split planes (fp16)
__device__ __half g_ahE[(size_t)M_ * E_];
__device__ __half g_alE[(size_t)M_ * E_];
__device__ __half g_ahF[(size_t)M_ * FF_];
__device__ __half g_alF[(size_t)M_ * FF_];
// weights: single fp16 plane
__device__ __half g_wqkv[(size_t)L_ * E_ * QKVN];
__device__ __half g_wo  [(size_t)L_ * E_ * E_];
__device__ __half g_w1  [(size_t)L_ * E_ * FF_];
__device__ __half g_w2  [(size_t)L_ * FF_ * E_];
__device__ __half g_wf  [(size_t)E_ * V_];

// ---------------- small helpers ----------------
__device__ __forceinline__ uint32_t pack_bf2(float a, float b) {
    __nv_bfloat162 t = __floats2bfloat162_rn(a, b);
    return *reinterpret_cast<uint32_t*>(&t);
}
__device__ __forceinline__ void split_write2_bf(float v0, float v1,
                                                __nv_bfloat16* ph, __nv_bfloat16* pl) {
    __nv_bfloat16 h0 = __float2bfloat16(v0), h1 = __float2bfloat16(v1);
    __nv_bfloat162 hh; hh.x = h0; hh.y = h1;
    *(__nv_bfloat162*)ph = hh;
    __nv_bfloat162 ll;
    ll.x = __float2bfloat16(v0 - __bfloat162float(h0));
    ll.y = __float2bfloat16(v1 - __bfloat162float(h1));
    *(__nv_bfloat162*)pl = ll;
}
__device__ __forceinline__ void split_write2_h(float v0, float v1,
                                               __half* ph, __half* pl) {
    __half h0 = __float2half_rn(v0), h1 = __float2half_rn(v1);
    *(__half2*)ph = __halves2half2(h0, h1);
    *(__half2*)pl = __halves2half2(__float2half_rn(v0 - __half2float(h0)),
                                   __float2half_rn(v1 - __half2float(h1)));
}
__device__ __forceinline__ void split_pack2_bf(float a, float b, uint32_t& hi, uint32_t& lo) {
    __nv_bfloat16 ha = __float2bfloat16(a), hb = __float2bfloat16(b);
    __nv_bfloat162 hh; hh.x = ha; hh.y = hb;
    hi = *reinterpret_cast<uint32_t*>(&hh);
    lo = pack_bf2(a - __bfloat162float(ha), b - __bfloat162float(hb));
}

// ---------------- embedding ----------------
__global__ void embed_kernel(const int* __restrict__ tokens,
                             const float* __restrict__ tok_emb,
                             const float* __restrict__ pos_emb,
                             float* __restrict__ x)
{
    int row = blockIdx.x;
    int s   = row % S_;
    int t   = tokens[row];
    const float4* te = (const float4*)(tok_emb + (size_t)t * E_);
    const float4* pe = (const float4*)(pos_emb + (size_t)s * E_);
    float4*       xo = (float4*)(x + (size_t)row * E_);
    for (int i = threadIdx.x; i < E_ / 4; i += blockDim.x) {
        float4 a = te[i], b = pe[i];
        xo[i] = make_float4(a.x + b.x, a.y + b.y, a.z + b.z, a.w + b.w);
    }
}

// ---------------- layernorm -> fp16 split planes (single-pass, register-resident) ----------------
__global__ void __launch_bounds__(256)
ln_split_kernel(const float* __restrict__ x,
                const float* __restrict__ g,
                const float* __restrict__ b,
                __half* __restrict__ oh,
                __half* __restrict__ ol)
{
    int row = blockIdx.x;
    int tid = threadIdx.x;
    __shared__ float red[256];
    const float4* xr4 = (const float4*)(x + (size_t)row * E_);

    float4 v = make_float4(0.f, 0.f, 0.f, 0.f);
    bool act = tid < E_ / 4;          // 192 active
    if (act) v = xr4[tid];

    float s = v.x + v.y + v.z + v.w;
    red[tid] = s; __syncthreads();
    for (int o = 128; o > 0; o >>= 1) { if (tid < o) red[tid] += red[tid + o]; __syncthreads(); }
    float mean = red[0] * (1.f / E_);
    __syncthreads();

    float sq = 0.f;
    if (act) {
        float d0 = v.x - mean, d1 = v.y - mean, d2 = v.z - mean, d3 = v.w - mean;
        sq = d0 * d0 + d1 * d1 + d2 * d2 + d3 * d3;
    }
    red[tid] = sq; __syncthreads();
    for (int o = 128; o > 0; o >>= 1) { if (tid < o) red[tid] += red[tid + o]; __syncthreads(); }
    float inv = rsqrtf(red[0] * (1.f / E_) + 1e-5f);

    if (act) {
        float4 g4 = ((const float4*)g)[tid];
        float4 b4 = ((const float4*)b)[tid];
        float y0 = (v.x - mean) * inv * g4.x + b4.x;
        float y1 = (v.y - mean) * inv * g4.y + b4.y;
        float y2 = (v.z - mean) * inv * g4.z + b4.z;
        float y3 = (v.w - mean) * inv * g4.w + b4.w;
        int col = tid * 4;
        __half* ohr = oh + (size_t)row * E_ + col;
        __half* olr = ol + (size_t)row * E_ + col;
        split_write2_h(y0, y1, ohr,     olr);
        split_write2_h(y2, y3, ohr + 2, olr + 2);
    }
}

// ---------------- fused weight conversion: all tensors, one launch ----------------
#define CS0 (L_ * E_ * E_ / 4)      // per tensor: Wq / Wk / Wv / Wo
#define CS1 (L_ * E_ * FF_ / 4)     // W1 / W2
#define CS2 (E_ * V_ / 4)           // Wf
#define CTOTAL (4 * CS0 + 2 * CS1 + CS2)
__global__ void convert_all_kernel(const float4* __restrict__ Wq4, const float4* __restrict__ Wk4,
                                   const float4* __restrict__ Wv4, const float4* __restrict__ Wo4,
                                   const float4* __restrict__ W14, const float4* __restrict__ W24,
                                   const float4* __restrict__ Wf4,
                                   uint2* __restrict__ wqkv_u, uint2* __restrict__ wo_u,
                                   uint2* __restrict__ w1_u, uint2* __restrict__ w2_u,
                                   uint2* __restrict__ wf_u)
{
    for (int idx = blockIdx.x * blockDim.x + threadIdx.x; idx < CTOTAL;
         idx += gridDim.x * blockDim.x) {
        float4 w;
        uint2* dst;
        if (idx < 3 * CS0) {                         // Q|K|V -> interleaved wqkv
            int which = idx / CS0;
            int r = idx - which * CS0;
            const float4* src = (which == 0) ? Wq4 : (which == 1) ? Wk4 : Wv4;
            w = src[r];
            int l  = r / (E_ * E_ / 4);
            int rr = r - l * (E_ * E_ / 4);
            int row = rr / (E_ / 4);
            int n4  = rr - row * (E_ / 4);
            dst = wqkv_u + ((size_t)l * E_ + row) * (QKVN / 4) + which * (E_ / 4) + n4;
        } else if (idx < 4 * CS0) {                  // Wo linear
            int r = idx - 3 * CS0;
            w = Wo4[r]; dst = wo_u + r;
        } else if (idx < 4 * CS0 + CS1) {            // W1 linear
            int r = idx - 4 * CS0;
            w = W14[r]; dst = w1_u + r;
        } else if (idx < 4 * CS0 + 2 * CS1) {        // W2 linear
            int r = idx - 4 * CS0 - CS1;
            w = W24[r]; dst = w2_u + r;
        } else {                                     // Wf linear
            int r = idx - 4 * CS0 - 2 * CS1;
            w = Wf4[r]; dst = wf_u + r;
        }
        __half2 p0 = __floats2half2_rn(w.x, w.y);
        __half2 p1 = __floats2half2_rn(w.z, w.w);
        uint2 hv;
        hv.x = *reinterpret_cast<uint32_t*>(&p0);
        hv.y = *reinterpret_cast<uint32_t*>(&p1);
        *dst = hv;
    }
}

__global__ void concat_bias_kernel(const float* __restrict__ bq,
                                   const float* __restrict__ bk,
                                   const float* __restrict__ bv,
                                   float* __restrict__ bqkv)
{
    int t = blockIdx.x * blockDim.x + threadIdx.x;
    if (t >= L_ * QKVN) return;
    int l = t / QKVN, c = t - l * QKVN;
    float v;
    if (c < E_)           v = bq[l * E_ + c];
    else if (c < 2 * E_)  v = bk[l * E_ + c - E_];
    else                  v = bv[l * E_ + c - 2 * E_];
    bqkv[t] = v;
}

// ---------------- PTX helpers ----------------
__device__ __forceinline__ void cp_async16(uint32_t s, const void* g) {
    asm volatile("cp.async.cg.shared.global [%0], [%1], 16;" :: "r"(s), "l"(g));
}
__device__ __forceinline__ void cp_commit() {
    asm volatile("cp.async.commit_group;");
}
template<int N>
__device__ __forceinline__ void cp_wait() {
    asm volatile("cp.async.wait_group %0;" :: "n"(N));
}
__device__ __forceinline__ void ldm_x4(uint32_t* r, uint32_t addr) {
    asm volatile("ldmatrix.sync.aligned.m8n8.x4.shared.b16 {%0,%1,%2,%3}, [%4];"
                 : "=r"(r[0]), "=r"(r[1]), "=r"(r[2]), "=r"(r[3]) : "r"(addr));
}
__device__ __forceinline__ void ldm_x4_trans(uint32_t* r, uint32_t addr) {
    asm volatile("ldmatrix.sync.aligned.m8n8.x4.trans.shared.b16 {%0,%1,%2,%3}, [%4];"
                 : "=r"(r[0]), "=r"(r[1]), "=r"(r[2]), "=r"(r[3]) : "r"(addr));
}
__device__ __forceinline__ void mma_bf16(float* d, const uint32_t* a, const uint32_t* b) {
    asm volatile(
        "mma.sync.aligned.m16n8k16.row.col.f32.bf16.bf16.f32 "
        "{%0,%1,%2,%3}, {%4,%5,%6,%7}, {%8,%9}, {%0,%1,%2,%3};"
        : "+f"(d[0]), "+f"(d[1]), "+f"(d[2]), "+f"(d[3])
        : "r"(a[0]), "r"(a[1]), "r"(a[2]), "r"(a[3]), "r"(b[0]), "r"(b[1]));
}
__device__ __forceinline__ void mma_f16(float* d, const uint32_t* a, const uint32_t* b) {
    asm volatile(
        "mma.sync.aligned.m16n8k16.row.col.f32.f16.f16.f32 "
        "{%0,%1,%2,%3}, {%4,%5,%6,%7}, {%8,%9}, {%0,%1,%2,%3};"
        : "+f"(d[0]), "+f"(d[1]), "+f"(d[2]), "+f"(d[3])
        : "r"(a[0]), "r"(a[1]), "r"(a[2]), "r"(a[3]), "r"(b[0]), "r"(b[1]));
}

// ---------------- fp16 2-term tensor-core GEMM, 4-stage cp.async pipeline ----------------
// C[M,N] = Ah@Bf + Al@Bf  (A exact as fp16 pair, B single-rounded fp16).
// OUT: 0 = fp32 C (bias/res), 2 = bf16 split planes, 3 = fp16 split planes
#define GLDA 40
#define GLDB 136
#define GSTAGES 4
#define GABYTES (128 * GLDA * 2)
#define GBBYTES (32 * GLDB * 2)
#define GSMEM (GSTAGES * (GABYTES + GBBYTES))   // 75776 B
template<int OUT, bool BIAS, bool RES, bool GELU>
__global__ void __launch_bounds__(256)
bgemm2_kernel(const __half* __restrict__ Ah, const __half* __restrict__ Al,
              const __half* __restrict__ Bf,
              const float* __restrict__ bias, const float* __restrict__ res,
              float* __restrict__ Cf,
              __nv_bfloat16* __restrict__ Cbh, __nv_bfloat16* __restrict__ Cbl,
              __half* __restrict__ Chh, __half* __restrict__ Chl,
              int Nd, int Kd)
{
    extern __shared__ __half dsm[];

    int tid  = threadIdx.x;
    int lane = tid & 31, wid = tid >> 5;
    int wm = wid & 3, wn = wid >> 2;
    int row0 = blockIdx.x * 128, col0 = blockIdx.y * 128;

    uint32_t as0 = (uint32_t)__cvta_generic_to_shared(dsm);
    uint32_t bs0 = as0 + GSTAGES * GABYTES;

    float acc[2][8][4];
    #pragma unroll
    for (int i = 0; i < 2; ++i)
        #pragma unroll
        for (int j = 0; j < 8; ++j)
            #pragma unroll
            for (int t = 0; t < 4; ++t) acc[i][j][t] = 0.f;

    const int KSEG = Kd / 32;
    const int KT   = 2 * KSEG;

    auto load_tile = [&](int buf, int kt) {
        int seg = (kt < KSEG) ? 0 : 1;
        const __half* Ab = seg ? Al : Ah;
        int k0 = (kt - seg * KSEG) * 32;
        uint32_t ab = as0 + buf * GABYTES;
        uint32_t bb = bs0 + buf * GBBYTES;
        #pragma unroll
        for (int i = 0; i < 2; ++i) {
            int chunk = tid * 2 + i;
            int m = chunk >> 2, c = chunk & 3;
            const void* g = Ab + (size_t)(row0 + m) * Kd + k0 + c * 8;
            cp_async16(ab + (uint32_t)(m * GLDA + c * 8) * 2, g);
        }
        #pragma unroll
        for (int i = 0; i < 2; ++i) {
            int chunk = tid * 2 + i;
            int k = chunk >> 4, c = chunk & 15;
            const void* g = Bf + (size_t)(k0 + k) * Nd + col0 + c * 8;
            cp_async16(bb + (uint32_t)(k * GLDB + c * 8) * 2, g);
        }
    };

    #pragma unroll
    for (int p = 0; p < GSTAGES - 1; ++p) {
        if (p < KT) load_tile(p, p);
        cp_commit();
    }

    for (int kt = 0; kt < KT; ++kt) {
        cp_wait<GSTAGES - 2>();
        __syncthreads();
        int buf = kt & (GSTAGES - 1);
        uint32_t ab = as0 + buf * GABYTES;
        uint32_t bb = bs0 + buf * GBBYTES;

        #pragma unroll
        for (int kk = 0; kk < 2; ++kk) {
            uint32_t af[2][4];
            #pragma unroll
            for (int mi = 0; mi < 2; ++mi) {
                int m  = wm * 32 + mi * 16 + (lane & 15);
                int kc = kk * 16 + (lane >> 4) * 8;
                ldm_x4(af[mi], ab + (uint32_t)(m * GLDA + kc) * 2);
            }
            uint32_t bfrag[8][2];
            #pragma unroll
            for (int ni4 = 0; ni4 < 4; ++ni4) {
                int g    = lane >> 3;
                int krow = kk * 16 + (g & 1) * 8 + (lane & 7);
                int ncol = wn * 64 + ni4 * 16 + (g >> 1) * 8;
                uint32_t r[4];
                ldm_x4_trans(r, bb + (uint32_t)(krow * GLDB + ncol) * 2);
                bfrag[2 * ni4][0] = r[0]; bfrag[2 * ni4][1] = r[1];
                bfrag[2 * ni4 + 1][0] = r[2]; bfrag[2 * ni4 + 1][1] = r[3];
            }
            #pragma unroll
            for (int mi = 0; mi < 2; ++mi)
                #pragma unroll
                for (int ni = 0; ni < 8; ++ni)
                    mma_f16(acc[mi][ni], af[mi], bfrag[ni]);
        }

        int nx = kt + GSTAGES - 1;
        if (nx < KT) load_tile(nx & (GSTAGES - 1), nx);
        cp_commit();
    }

    // epilogue
    #pragma unroll
    for (int mi = 0; mi < 2; ++mi) {
        int r = row0 + wm * 32 + mi * 16 + (lane >> 2);
        #pragma unroll
        for (int ni = 0; ni < 8; ++ni) {
            int c = col0 + wn * 64 + ni * 8 + (lane & 3) * 2;
            float b0 = 0.f, b1 = 0.f;
            if (BIAS) { b0 = bias[c]; b1 = bias[c + 1]; }
            #pragma unroll
            for (int half = 0; half < 2; ++half) {
                int rr = r + half * 8;
                float v0 = acc[mi][ni][half * 2 + 0] + b0;
                float v1 = acc[mi][ni][half * 2 + 1] + b1;
                if (GELU) {
                    v0 = 0.5f * v0 * (1.f + erff(v0 * 0.70710678118654752f));
                    v1 = 0.5f * v1 * (1.f + erff(v1 * 0.70710678118654752f));
                }
                if (RES) {
                    const float2 rv = *(const float2*)(res + (size_t)rr * Nd + c);
                    v0 += rv.x; v1 += rv.y;
                }
                if (OUT == 0) {
                    *(float2*)(Cf + (size_t)rr * Nd + c) = make_float2(v0, v1);
                } else if (OUT == 2) {
                    split_write2_bf(v0, v1, Cbh + (size_t)rr * Nd + c, Cbl + (size_t)rr * Nd + c);
                } else {
                    split_write2_h(v0, v1, Chh + (size_t)rr * Nd + c, Chl + (size_t)rr * Nd + c);
                }
            }
        }
    }
}

// ---------------- flash attention (split-3 bf16, 64-row Q tiles, 128 threads) ----------------
// qkvh/qkvl: [M, 2304] bf16 split planes.  Heavy tiles launch first (reversed it).
#define LDQ 72
#define FA_TILE (64 * LDQ)
#define FA_SMEM (6 * FA_TILE * 2)   // 55296 B
__global__ void __launch_bounds__(128)
flash_kernel(const __nv_bfloat16* __restrict__ qkvh,
             const __nv_bfloat16* __restrict__ qkvl,
             __half* __restrict__ oh, __half* __restrict__ ol)
{
    extern __shared__ __nv_bfloat16 smem[];
    __nv_bfloat16* Qh = smem;
    __nv_bfloat16* Ql = Qh + FA_TILE;
    __nv_bfloat16* Kh = Ql + FA_TILE;
    __nv_bfloat16* Kl = Kh + FA_TILE;
    __nv_bfloat16* Vh = Kl + FA_TILE;
    __nv_bfloat16* Vl = Vh + FA_TILE;

    int it = (S_ / 64 - 1) - blockIdx.x;   // heavy causal tiles first
    int z  = blockIdx.y;
    int b = z / H_, h = z % H_;
    int tid = threadIdx.x, lane = tid & 31, wm = tid >> 5;
    size_t rowbase = (size_t)b * S_;

    {
        size_t qoff = (rowbase + it * 64) * QKVN + h * D_;
        for (int cc = tid; cc < 512; cc += 128) {
            int r = cc >> 3, c = cc & 7;
            *(uint4*)&Qh[r * LDQ + c * 8] = *(const uint4*)(qkvh + qoff + (size_t)r * QKVN + c * 8);
            *(uint4*)&Ql[r * LDQ + c * 8] = *(const uint4*)(qkvl + qoff + (size_t)r * QKVN + c * 8);
        }
    }
    uint32_t qh_s = (uint32_t)__cvta_generic_to_shared(Qh);
    uint32_t ql_s = (uint32_t)__cvta_generic_to_shared(Ql);
    uint32_t kh_s = (uint32_t)__cvta_generic_to_shared(Kh);
    uint32_t kl_s = (uint32_t)__cvta_generic_to_shared(Kl);
    uint32_t vh_s = (uint32_t)__cvta_generic_to_shared(Vh);
    uint32_t vl_s = (uint32_t)__cvta_generic_to_shared(Vl);

    float oacc[8][4];
    #pragma unroll
    for (int j = 0; j < 8; ++j)
        #pragma unroll
        for (int t = 0; t < 4; ++t) oacc[j][t] = 0.f;
    float m_prev[2] = { -1e30f, -1e30f };
    float lsum[2]   = { 0.f, 0.f };

    for (int jt = 0; jt <= it; ++jt) {
        __syncthreads();
        size_t koff = (rowbase + jt * 64) * QKVN + E_ + h * D_;
        size_t voff = koff + E_;
        for (int cc = tid; cc < 512; cc += 128) {
            int r = cc >> 3, c = cc & 7;
            size_t gr = (size_t)r * QKVN + c * 8;
            int so = r * LDQ + c * 8;
            *(uint4*)&Kh[so] = *(const uint4*)(qkvh + koff + gr);
            *(uint4*)&Kl[so] = *(const uint4*)(qkvl + koff + gr);
            *(uint4*)&Vh[so] = *(const uint4*)(qkvh + voff + gr);
            *(uint4*)&Vl[so] = *(const uint4*)(qkvl + voff + gr);
        }
        __syncthreads();

        float sacc[8][4];
        #pragma unroll
        for (int j = 0; j < 8; ++j)
            #pragma unroll
            for (int t = 0; t < 4; ++t) sacc[j][t] = 0.f;

        #pragma unroll
        for (int kc = 0; kc < 4; ++kc) {
            uint32_t a_off = (uint32_t)((wm * 16 + (lane & 15)) * LDQ + kc * 16 + (lane >> 4) * 8) * 2;
            uint32_t afh[4], afl[4];
            ldm_x4(afh, qh_s + a_off);
            ldm_x4(afl, ql_s + a_off);
            #pragma unroll
            for (int np = 0; np < 4; ++np) {
                int nrow = np * 16 + (lane & 7) + ((lane >> 4) << 3);
                int ncol = kc * 16 + ((lane >> 3) & 1) * 8;
                uint32_t b_off = (uint32_t)(nrow * LDQ + ncol) * 2;
                uint32_t brh[4], brl[4];
                ldm_x4(brh, kh_s + b_off);
                ldm_x4(brl, kl_s + b_off);
                mma_bf16(sacc[np * 2],     afh, brh);
                mma_bf16(sacc[np * 2],     afh, brl);
                mma_bf16(sacc[np * 2],     afl, brh);
                mma_bf16(sacc[np * 2 + 1], afh, brh + 2);
                mma_bf16(sacc[np * 2 + 1], afh, brl + 2);
                mma_bf16(sacc[np * 2 + 1], afl, brh + 2);
            }
        }

        int rloc = wm * 16 + (lane >> 2);
        float mtile[2] = { -1e30f, -1e30f };
        bool diag = (jt == it);
        #pragma unroll
        for (int j = 0; j < 8; ++j) {
            int cg = jt * 64 + j * 8 + (lane & 3) * 2;
            #pragma unroll
            for (int rh = 0; rh < 2; ++rh) {
                int rg = it * 64 + rloc + rh * 8;
                float s0 = sacc[j][rh * 2]     * 0.125f;
                float s1 = sacc[j][rh * 2 + 1] * 0.125f;
                if (diag) {
                    if (cg     > rg) s0 = -1e30f;
                    if (cg + 1 > rg) s1 = -1e30f;
                }
                sacc[j][rh * 2]     = s0;
                sacc[j][rh * 2 + 1] = s1;
                mtile[rh] = fmaxf(mtile[rh], fmaxf(s0, s1));
            }
        }
        #pragma unroll
        for (int rh = 0; rh < 2; ++rh) {
            mtile[rh] = fmaxf(mtile[rh], __shfl_xor_sync(0xffffffff, mtile[rh], 1));
            mtile[rh] = fmaxf(mtile[rh], __shfl_xor_sync(0xffffffff, mtile[rh], 2));
        }
        float alpha[2];
        #pragma unroll
        for (int rh = 0; rh < 2; ++rh) {
            float mn = fmaxf(m_prev[rh], mtile[rh]);
            alpha[rh] = __expf(m_prev[rh] - mn);
            m_prev[rh] = mn;
        }
        float rsum[2] = { 0.f, 0.f };
        #pragma unroll
        for (int j = 0; j < 8; ++j)
            #pragma unroll
            for (int rh = 0; rh < 2; ++rh) {
                float p0 = __expf(sacc[j][rh * 2]     - m_prev[rh]);
                float p1 = __expf(sacc[j][rh * 2 + 1] - m_prev[rh]);
                sacc[j][rh * 2] = p0; sacc[j][rh * 2 + 1] = p1;
                rsum[rh] += p0 + p1;
            }
        #pragma unroll
        for (int rh = 0; rh < 2; ++rh) {
            rsum[rh] += __shfl_xor_sync(0xffffffff, rsum[rh], 1);
            rsum[rh] += __shfl_xor_sync(0xffffffff, rsum[rh], 2);
            lsum[rh] = lsum[rh] * alpha[rh] + rsum[rh];
        }
        #pragma unroll
        for (int j = 0; j < 8; ++j)
            #pragma unroll
            for (int rh = 0; rh < 2; ++rh) {
                oacc[j][rh * 2]     *= alpha[rh];
                oacc[j][rh * 2 + 1] *= alpha[rh];
            }
        #pragma unroll
        for (int kc = 0; kc < 4; ++kc) {
            uint32_t pah[4], pal[4];
            split_pack2_bf(sacc[2 * kc][0],     sacc[2 * kc][1],     pah[0], pal[0]);
            split_pack2_bf(sacc[2 * kc][2],     sacc[2 * kc][3],     pah[1], pal[1]);
            split_pack2_bf(sacc[2 * kc + 1][0], sacc[2 * kc + 1][1], pah[2], pal[2]);
            split_pack2_bf(sacc[2 * kc + 1][2], sacc[2 * kc + 1][3], pah[3], pal[3]);
            #pragma unroll
            for (int np = 0; np < 4; ++np) {
                int g = lane >> 3;
                int krow = kc * 16 + (g & 1) * 8 + (lane & 7);
                int ncol = np * 16 + (g >> 1) * 8;
                uint32_t v_off = (uint32_t)(krow * LDQ + ncol) * 2;
                uint32_t brh[4], brl[4];
                ldm_x4_trans(brh, vh_s + v_off);
                ldm_x4_trans(brl, vl_s + v_off);
                mma_bf16(oacc[np * 2],     pah, brh);
                mma_bf16(oacc[np * 2],     pah, brl);
                mma_bf16(oacc[np * 2],     pal, brh);
                mma_bf16(oacc[np * 2 + 1], pah, brh + 2);
                mma_bf16(oacc[np * 2 + 1], pah, brl + 2);
                mma_bf16(oacc[np * 2 + 1], pal, brh + 2);
            }
        }
    }

    float inv[2] = { 1.f / lsum[0], 1.f / lsum[1] };
    size_t gr0 = rowbase + it * 64 + wm * 16 + (lane >> 2);
    #pragma unroll
    for (int j = 0; j < 8; ++j) {
        int col = h * D_ + j * 8 + (lane & 3) * 2;
        #pragma unroll
        for (int rh = 0; rh < 2; ++rh) {
            size_t gr = gr0 + rh * 8;
            float v0 = oacc[j][rh * 2]     * inv[rh];
            float v1 = oacc[j][rh * 2 + 1] * inv[rh];
            split_write2_h(v0, v1, oh + gr * E_ + col, ol + gr * E_ + col);
        }
    }
}

// ---------------- host launcher ----------------
extern "C" void kernel_launch(void* const* d_in, const int* in_sizes, int n_in,
                              void* d_out, int out_size)
{
    const int*   tokens  = (const int*)  d_in[0];
    const float* tok_emb = (const float*)d_in[1];
    const float* pos_emb = (const float*)d_in[2];
    const float* Wq = (const float*)d_in[3];
    const float* bq = (const float*)d_in[4];
    const float* Wk = (const float*)d_in[5];
    const float* bk = (const float*)d_in[6];
    const float* Wv = (const float*)d_in[7];
    const float* bv = (const float*)d_in[8];
    const float* Wo = (const float*)d_in[9];
    const float* bo = (const float*)d_in[10];
    const float* ln1_g = (const float*)d_in[11];
    const float* ln1_b = (const float*)d_in[12];
    const float* ln2_g = (const float*)d_in[13];
    const float* ln2_b = (const float*)d_in[14];
    const float* W1 = (const float*)d_in[15];
    const float* b1 = (const float*)d_in[16];
    const float* W2 = (const float*)d_in[17];
    const float* b2 = (const float*)d_in[18];
    const float* lnf_g = (const float*)d_in[19];
    const float* lnf_b = (const float*)d_in[20];
    const float* Wf = (const float*)d_in[21];
    const float* bf = (const float*)d_in[22];
    float* out = (float*)d_out;

    float *x, *bqkv;
    __nv_bfloat16 *qkvh, *qkvl;
    __half *ahE, *alE, *ahF, *alF;
    __half *wqkv, *wo, *w1, *w2, *wf;
    cudaGetSymbolAddress((void**)&x,    g_x);
    cudaGetSymbolAddress((void**)&bqkv, g_bqkv);
    cudaGetSymbolAddress((void**)&qkvh, g_qkvh);
    cudaGetSymbolAddress((void**)&qkvl, g_qkvl);
    cudaGetSymbolAddress((void**)&ahE,  g_ahE);
    cudaGetSymbolAddress((void**)&alE,  g_alE);
    cudaGetSymbolAddress((void**)&ahF,  g_ahF);
    cudaGetSymbolAddress((void**)&alF,  g_alF);
    cudaGetSymbolAddress((void**)&wqkv, g_wqkv);
    cudaGetSymbolAddress((void**)&wo,   g_wo);
    cudaGetSymbolAddress((void**)&w1,   g_w1);
    cudaGetSymbolAddress((void**)&w2,   g_w2);
    cudaGetSymbolAddress((void**)&wf,   g_wf);

    const size_t EE = (size_t)E_ * E_;
    cudaFuncSetAttribute(flash_kernel, cudaFuncAttributeMaxDynamicSharedMemorySize, FA_SMEM);
    cudaFuncSetAttribute(bgemm2_kernel<2, true, false, false>,
                         cudaFuncAttributeMaxDynamicSharedMemorySize, GSMEM);
    cudaFuncSetAttribute(bgemm2_kernel<0, true, true, false>,
                         cudaFuncAttributeMaxDynamicSharedMemorySize, GSMEM);
    cudaFuncSetAttribute(bgemm2_kernel<3, true, false, true>,
                         cudaFuncAttributeMaxDynamicSharedMemorySize, GSMEM);
    cudaFuncSetAttribute(bgemm2_kernel<0, true, false, false>,
                         cudaFuncAttributeMaxDynamicSharedMemorySize, GSMEM);

    // ---- fused weight conversion (one launch) ----
    convert_all_kernel<<<4096, 256>>>(
        (const float4*)Wq, (const float4*)Wk, (const float4*)Wv, (const float4*)Wo,
        (const float4*)W1, (const float4*)W2, (const float4*)Wf,
        (uint2*)wqkv, (uint2*)wo, (uint2*)w1, (uint2*)w2, (uint2*)wf);
    concat_bias_kernel<<<(L_ * QKVN + 255) / 256, 256>>>(bq, bk, bv, bqkv);

    embed_kernel<<<M_, 192>>>(tokens, tok_emb, pos_emb, x);

    dim3 gQKV (M_ / 128, QKVN / 128);   // 16 x 18
    dim3 gProj(M_ / 128, E_ / 128);     // 16 x 6
    dim3 gFF1 (M_ / 128, FF_ / 128);    // 16 x 36
    dim3 gHead(M_ / 128, V_ / 128);     // 16 x 250
    dim3 gFA  (S_ / 64, B_ * H_);       // 16 x 24

    for (int l = 0; l < L_; ++l) {
        size_t qoff = (size_t)l * E_ * QKVN;
        size_t ooff = (size_t)l * EE;
        size_t f1 = (size_t)l * E_ * FF_;
        size_t f2 = (size_t)l * FF_ * E_;

        ln_split_kernel<<<M_, 256>>>(x, ln1_g + l * E_, ln1_b + l * E_, ahE, alE);

        // qkv = h @ Wqkv + b   -> bf16 split planes (qkvh, qkvl)
        bgemm2_kernel<2, true, false, false><<<gQKV, 256, GSMEM>>>(
            ahE, alE, wqkv + qoff, bqkv + l * QKVN, nullptr,
            nullptr, qkvh, qkvl, nullptr, nullptr, QKVN, E_);

        // o -> fp16 split planes
        flash_kernel<<<gFA, 128, FA_SMEM>>>(qkvh, qkvl, ahE, alE);

        // x = x + o @ Wo + bo
        bgemm2_kernel<0, true, true, false><<<gProj, 256, GSMEM>>>(
            ahE, alE, wo + ooff, bo + l * E_, x,
            x, nullptr, nullptr, nullptr, nullptr, E_, E_);

        ln_split_kernel<<<M_, 256>>>(x, ln2_g + l * E_, ln2_b + l * E_, ahE, alE);

        // ff = gelu(h @ W1 + b1) -> fp16 split planes
        bgemm2_kernel<3, true, false, true><<<gFF1, 256, GSMEM>>>(
            ahE, alE, w1 + f1, b1 + l * FF_, nullptr,
            nullptr, nullptr, nullptr, ahF, alF, FF_, E_);

        // x = x + ff @ W2 + b2
        bgemm2_kernel<0, true, true, false><<<gProj, 256, GSMEM>>>(
            ahF, alF, w2 + f2, b2 + l * E_, x,
            x, nullptr, nullptr, nullptr, nullptr, E_, FF_);
    }

    ln_split_kernel<<<M_, 256>>>(x, lnf_g, lnf_b, ahE, alE);
    bgemm2_kernel<0, true, false, false><<<gHead, 256, GSMEM>>>(
        ahE, alE, wf, bf, nullptr,
        out, nullptr, nullptr, nullptr, nullptr, V_, E_);
}

// round 15
// speedup vs baseline: 1.2093x; 1.1280x over previous
#include <cuda_runtime.h>
#include <cuda_bf16.h>
#include <cuda_fp16.h>
#include <math.h>
#include <stdint.h>

// Problem dims (compile-time)
#define E_  768
#define H_  12
#define D_  64
#define L_  4
#define S_  1024
#define B_  2
#define V_  32000
#define FF_ 4608
#define M_  (B_ * S_)   // 2048 rows
#define QKVN 2304       // 3*E

// ---------------- scratch ----------------
__device__ float g_x[M_ * E_];
__device__ float g_bqkv[L_ * QKVN];
__device__ __nv_bfloat16 g_qkvh[(size_t)M_ * QKVN];
__device__ __nv_bfloat16 g_qkvl[(size_t)M_ * QKVN];
__device__ __half g_ahE[(size_t)M_ * E_];
__device__ __half g_alE[(size_t)M_ * E_];
__device__ __half g_ahF[(size_t)M_ * FF_];
__device__ __half g_alF[(size_t)M_ * FF_];
__device__ __half g_wqkv[(size_t)L_ * E_ * QKVN];
__device__ __half g_wo  [(size_t)L_ * E_ * E_];
__device__ __half g_w1  [(size_t)L_ * E_ * FF_];
__device__ __half g_w2  [(size_t)L_ * FF_ * E_];
__device__ __half g_wf  [(size_t)E_ * V_];

// ---------------- small helpers ----------------
__device__ __forceinline__ uint32_t pack_bf2(float a, float b) {
    __nv_bfloat162 t = __floats2bfloat162_rn(a, b);
    return *reinterpret_cast<uint32_t*>(&t);
}
__device__ __forceinline__ void split_write2_bf(float v0, float v1,
                                                __nv_bfloat16* ph, __nv_bfloat16* pl) {
    __nv_bfloat16 h0 = __float2bfloat16(v0), h1 = __float2bfloat16(v1);
    __nv_bfloat162 hh; hh.x = h0; hh.y = h1;
    *(__nv_bfloat162*)ph = hh;
    __nv_bfloat162 ll;
    ll.x = __float2bfloat16(v0 - __bfloat162float(h0));
    ll.y = __float2bfloat16(v1 - __bfloat162float(h1));
    *(__nv_bfloat162*)pl = ll;
}
__device__ __forceinline__ void split_write2_h(float v0, float v1,
                                               __half* ph, __half* pl) {
    __half h0 = __float2half_rn(v0), h1 = __float2half_rn(v1);
    *(__half2*)ph = __halves2half2(h0, h1);
    *(__half2*)pl = __halves2half2(__float2half_rn(v0 - __half2float(h0)),
                                   __float2half_rn(v1 - __half2float(h1)));
}
__device__ __forceinline__ void split_pack2_bf(float a, float b, uint32_t& hi, uint32_t& lo) {
    __nv_bfloat16 ha = __float2bfloat16(a), hb = __float2bfloat16(b);
    __nv_bfloat162 hh; hh.x = ha; hh.y = hb;
    hi = *reinterpret_cast<uint32_t*>(&hh);
    lo = pack_bf2(a - __bfloat162float(ha), b - __bfloat162float(hb));
}

// ---------------- embedding ----------------
__global__ void embed_kernel(const int* __restrict__ tokens,
                             const float* __restrict__ tok_emb,
                             const float* __restrict__ pos_emb,
                             float* __restrict__ x)
{
    int row = blockIdx.x;
    int s   = row % S_;
    int t   = tokens[row];
    const float4* te = (const float4*)(tok_emb + (size_t)t * E_);
    const float4* pe = (const float4*)(pos_emb + (size_t)s * E_);
    float4*       xo = (float4*)(x + (size_t)row * E_);
    for (int i = threadIdx.x; i < E_ / 4; i += blockDim.x) {
        float4 a = te[i], b = pe[i];
        xo[i] = make_float4(a.x + b.x, a.y + b.y, a.z + b.z, a.w + b.w);
    }
}

// ---------------- layernorm -> fp16 split planes ----------------
__global__ void __launch_bounds__(256)
ln_split_kernel(const float* __restrict__ x,
                const float* __restrict__ g,
                const float* __restrict__ b,
                __half* __restrict__ oh,
                __half* __restrict__ ol)
{
    int row = blockIdx.x;
    int tid = threadIdx.x;
    __shared__ float red[256];
    const float4* xr4 = (const float4*)(x + (size_t)row * E_);

    float4 v = make_float4(0.f, 0.f, 0.f, 0.f);
    bool act = tid < E_ / 4;
    if (act) v = xr4[tid];

    float s = v.x + v.y + v.z + v.w;
    red[tid] = s; __syncthreads();
    for (int o = 128; o > 0; o >>= 1) { if (tid < o) red[tid] += red[tid + o]; __syncthreads(); }
    float mean = red[0] * (1.f / E_);
    __syncthreads();

    float sq = 0.f;
    if (act) {
        float d0 = v.x - mean, d1 = v.y - mean, d2 = v.z - mean, d3 = v.w - mean;
        sq = d0 * d0 + d1 * d1 + d2 * d2 + d3 * d3;
    }
    red[tid] = sq; __syncthreads();
    for (int o = 128; o > 0; o >>= 1) { if (tid < o) red[tid] += red[tid + o]; __syncthreads(); }
    float inv = rsqrtf(red[0] * (1.f / E_) + 1e-5f);

    if (act) {
        float4 g4 = ((const float4*)g)[tid];
        float4 b4 = ((const float4*)b)[tid];
        float y0 = (v.x - mean) * inv * g4.x + b4.x;
        float y1 = (v.y - mean) * inv * g4.y + b4.y;
        float y2 = (v.z - mean) * inv * g4.z + b4.z;
        float y3 = (v.w - mean) * inv * g4.w + b4.w;
        int col = tid * 4;
        __half* ohr = oh + (size_t)row * E_ + col;
        __half* olr = ol + (size_t)row * E_ + col;
        split_write2_h(y0, y1, ohr,     olr);
        split_write2_h(y2, y3, ohr + 2, olr + 2);
    }
}

// ---------------- fused weight conversion: all tensors, one launch ----------------
#define CS0 (L_ * E_ * E_ / 4)      // per tensor: Wq / Wk / Wv / Wo
#define CS1 (L_ * E_ * FF_ / 4)     // W1 / W2
#define CS2 (E_ * V_ / 4)           // Wf
#define CTOTAL (4 * CS0 + 2 * CS1 + CS2)
__global__ void convert_all_kernel(const float4* __restrict__ Wq4, const float4* __restrict__ Wk4,
                                   const float4* __restrict__ Wv4, const float4* __restrict__ Wo4,
                                   const float4* __restrict__ W14, const float4* __restrict__ W24,
                                   const float4* __restrict__ Wf4,
                                   uint2* __restrict__ wqkv_u, uint2* __restrict__ wo_u,
                                   uint2* __restrict__ w1_u, uint2* __restrict__ w2_u,
                                   uint2* __restrict__ wf_u)
{
    for (int idx = blockIdx.x * blockDim.x + threadIdx.x; idx < CTOTAL;
         idx += gridDim.x * blockDim.x) {
        float4 w;
        uint2* dst;
        if (idx < 3 * CS0) {                         // Q|K|V -> interleaved wqkv
            int which = idx / CS0;
            int r = idx - which * CS0;
            const float4* src = (which == 0) ? Wq4 : (which == 1) ? Wk4 : Wv4;
            w = src[r];
            int l  = r / (E_ * E_ / 4);
            int rr = r - l * (E_ * E_ / 4);
            int row = rr / (E_ / 4);
            int n4  = rr - row * (E_ / 4);
            dst = wqkv_u + ((size_t)l * E_ + row) * (QKVN / 4) + which * (E_ / 4) + n4;
        } else if (idx < 4 * CS0) {
            int r = idx - 3 * CS0;
            w = Wo4[r]; dst = wo_u + r;
        } else if (idx < 4 * CS0 + CS1) {
            int r = idx - 4 * CS0;
            w = W14[r]; dst = w1_u + r;
        } else if (idx < 4 * CS0 + 2 * CS1) {
            int r = idx - 4 * CS0 - CS1;
            w = W24[r]; dst = w2_u + r;
        } else {
            int r = idx - 4 * CS0 - 2 * CS1;
            w = Wf4[r]; dst = wf_u + r;
        }
        __half2 p0 = __floats2half2_rn(w.x, w.y);
        __half2 p1 = __floats2half2_rn(w.z, w.w);
        uint2 hv;
        hv.x = *reinterpret_cast<uint32_t*>(&p0);
        hv.y = *reinterpret_cast<uint32_t*>(&p1);
        *dst = hv;
    }
}

__global__ void concat_bias_kernel(const float* __restrict__ bq,
                                   const float* __restrict__ bk,
                                   const float* __restrict__ bv,
                                   float* __restrict__ bqkv)
{
    int t = blockIdx.x * blockDim.x + threadIdx.x;
    if (t >= L_ * QKVN) return;
    int l = t / QKVN, c = t - l * QKVN;
    float v;
    if (c < E_)           v = bq[l * E_ + c];
    else if (c < 2 * E_)  v = bk[l * E_ + c - E_];
    else                  v = bv[l * E_ + c - 2 * E_];
    bqkv[t] = v;
}

// ---------------- PTX helpers ----------------
__device__ __forceinline__ void cp_async16(uint32_t s, const void* g) {
    asm volatile("cp.async.cg.shared.global [%0], [%1], 16;" :: "r"(s), "l"(g));
}
__device__ __forceinline__ void cp_commit() {
    asm volatile("cp.async.commit_group;");
}
template<int N>
__device__ __forceinline__ void cp_wait() {
    asm volatile("cp.async.wait_group %0;" :: "n"(N));
}
__device__ __forceinline__ void ldm_x4(uint32_t* r, uint32_t addr) {
    asm volatile("ldmatrix.sync.aligned.m8n8.x4.shared.b16 {%0,%1,%2,%3}, [%4];"
                 : "=r"(r[0]), "=r"(r[1]), "=r"(r[2]), "=r"(r[3]) : "r"(addr));
}
__device__ __forceinline__ void ldm_x4_trans(uint32_t* r, uint32_t addr) {
    asm volatile("ldmatrix.sync.aligned.m8n8.x4.trans.shared.b16 {%0,%1,%2,%3}, [%4];"
                 : "=r"(r[0]), "=r"(r[1]), "=r"(r[2]), "=r"(r[3]) : "r"(addr));
}
__device__ __forceinline__ void mma_bf16(float* d, const uint32_t* a, const uint32_t* b) {
    asm volatile(
        "mma.sync.aligned.m16n8k16.row.col.f32.bf16.bf16.f32 "
        "{%0,%1,%2,%3}, {%4,%5,%6,%7}, {%8,%9}, {%0,%1,%2,%3};"
        : "+f"(d[0]), "+f"(d[1]), "+f"(d[2]), "+f"(d[3])
        : "r"(a[0]), "r"(a[1]), "r"(a[2]), "r"(a[3]), "r"(b[0]), "r"(b[1]));
}
__device__ __forceinline__ void mma_f16(float* d, const uint32_t* a, const uint32_t* b) {
    asm volatile(
        "mma.sync.aligned.m16n8k16.row.col.f32.f16.f16.f32 "
        "{%0,%1,%2,%3}, {%4,%5,%6,%7}, {%8,%9}, {%0,%1,%2,%3};"
        : "+f"(d[0]), "+f"(d[1]), "+f"(d[2]), "+f"(d[3])
        : "r"(a[0]), "r"(a[1]), "r"(a[2]), "r"(a[3]), "r"(b[0]), "r"(b[1]));
}

// ---------------- fp16 tensor-core GEMM, 4-stage cp.async pipeline ----------------
// TERMS=2: C = Ah@Bf + Al@Bf (A exact as fp16 pair).  TERMS=1: C = Ah@Bf.
// OUT: 0 = fp32 C (bias/res), 2 = bf16 split planes, 3 = fp16 split planes
#define GLDA 40
#define GLDB 136
#define GSTAGES 4
#define GABYTES (128 * GLDA * 2)
#define GBBYTES (32 * GLDB * 2)
#define GSMEM (GSTAGES * (GABYTES + GBBYTES))   // 75776 B
template<int TERMS, int OUT, bool BIAS, bool RES, bool GELU>
__global__ void __launch_bounds__(256)
bgemm2_kernel(const __half* __restrict__ Ah, const __half* __restrict__ Al,
              const __half* __restrict__ Bf,
              const float* __restrict__ bias, const float* __restrict__ res,
              float* __restrict__ Cf,
              __nv_bfloat16* __restrict__ Cbh, __nv_bfloat16* __restrict__ Cbl,
              __half* __restrict__ Chh, __half* __restrict__ Chl,
              int Nd, int Kd)
{
    extern __shared__ __half dsm[];

    int tid  = threadIdx.x;
    int lane = tid & 31, wid = tid >> 5;
    int wm = wid & 3, wn = wid >> 2;
    int row0 = blockIdx.x * 128, col0 = blockIdx.y * 128;

    uint32_t as0 = (uint32_t)__cvta_generic_to_shared(dsm);
    uint32_t bs0 = as0 + GSTAGES * GABYTES;

    float acc[2][8][4];
    #pragma unroll
    for (int i = 0; i < 2; ++i)
        #pragma unroll
        for (int j = 0; j < 8; ++j)
            #pragma unroll
            for (int t = 0; t < 4; ++t) acc[i][j][t] = 0.f;

    const int KSEG = Kd / 32;
    const int KT   = TERMS * KSEG;

    auto load_tile = [&](int buf, int kt) {
        int seg = (kt < KSEG) ? 0 : 1;
        const __half* Ab = seg ? Al : Ah;
        int k0 = (kt - seg * KSEG) * 32;
        uint32_t ab = as0 + buf * GABYTES;
        uint32_t bb = bs0 + buf * GBBYTES;
        #pragma unroll
        for (int i = 0; i < 2; ++i) {
            int chunk = tid * 2 + i;
            int m = chunk >> 2, c = chunk & 3;
            const void* g = Ab + (size_t)(row0 + m) * Kd + k0 + c * 8;
            cp_async16(ab + (uint32_t)(m * GLDA + c * 8) * 2, g);
        }
        #pragma unroll
        for (int i = 0; i < 2; ++i) {
            int chunk = tid * 2 + i;
            int k = chunk >> 4, c = chunk & 15;
            const void* g = Bf + (size_t)(k0 + k) * Nd + col0 + c * 8;
            cp_async16(bb + (uint32_t)(k * GLDB + c * 8) * 2, g);
        }
    };

    #pragma unroll
    for (int p = 0; p < GSTAGES - 1; ++p) {
        if (p < KT) load_tile(p, p);
        cp_commit();
    }

    for (int kt = 0; kt < KT; ++kt) {
        cp_wait<GSTAGES - 2>();
        __syncthreads();
        int buf = kt & (GSTAGES - 1);
        uint32_t ab = as0 + buf * GABYTES;
        uint32_t bb = bs0 + buf * GBBYTES;

        #pragma unroll
        for (int kk = 0; kk < 2; ++kk) {
            uint32_t af[2][4];
            #pragma unroll
            for (int mi = 0; mi < 2; ++mi) {
                int m  = wm * 32 + mi * 16 + (lane & 15);
                int kc = kk * 16 + (lane >> 4) * 8;
                ldm_x4(af[mi], ab + (uint32_t)(m * GLDA + kc) * 2);
            }
            uint32_t bfrag[8][2];
            #pragma unroll
            for (int ni4 = 0; ni4 < 4; ++ni4) {
                int g    = lane >> 3;
                int krow = kk * 16 + (g & 1) * 8 + (lane & 7);
                int ncol = wn * 64 + ni4 * 16 + (g >> 1) * 8;
                uint32_t r[4];
                ldm_x4_trans(r, bb + (uint32_t)(krow * GLDB + ncol) * 2);
                bfrag[2 * ni4][0] = r[0]; bfrag[2 * ni4][1] = r[1];
                bfrag[2 * ni4 + 1][0] = r[2]; bfrag[2 * ni4 + 1][1] = r[3];
            }
            #pragma unroll
            for (int mi = 0; mi < 2; ++mi)
                #pragma unroll
                for (int ni = 0; ni < 8; ++ni)
                    mma_f16(acc[mi][ni], af[mi], bfrag[ni]);
        }

        int nx = kt + GSTAGES - 1;
        if (nx < KT) load_tile(nx & (GSTAGES - 1), nx);
        cp_commit();
    }

    // epilogue
    #pragma unroll
    for (int mi = 0; mi < 2; ++mi) {
        int r = row0 + wm * 32 + mi * 16 + (lane >> 2);
        #pragma unroll
        for (int ni = 0; ni < 8; ++ni) {
            int c = col0 + wn * 64 + ni * 8 + (lane & 3) * 2;
            float b0 = 0.f, b1 = 0.f;
            if (BIAS) { b0 = bias[c]; b1 = bias[c + 1]; }
            #pragma unroll
            for (int half = 0; half < 2; ++half) {
                int rr = r + half * 8;
                float v0 = acc[mi][ni][half * 2 + 0] + b0;
                float v1 = acc[mi][ni][half * 2 + 1] + b1;
                if (GELU) {
                    v0 = 0.5f * v0 * (1.f + erff(v0 * 0.70710678118654752f));
                    v1 = 0.5f * v1 * (1.f + erff(v1 * 0.70710678118654752f));
                }
                if (RES) {
                    const float2 rv = *(const float2*)(res + (size_t)rr * Nd + c);
                    v0 += rv.x; v1 += rv.y;
                }
                if (OUT == 0) {
                    *(float2*)(Cf + (size_t)rr * Nd + c) = make_float2(v0, v1);
                } else if (OUT == 2) {
                    split_write2_bf(v0, v1, Cbh + (size_t)rr * Nd + c, Cbl + (size_t)rr * Nd + c);
                } else {
                    split_write2_h(v0, v1, Chh + (size_t)rr * Nd + c, Chl + (size_t)rr * Nd + c);
                }
            }
        }
    }
}

// ---------------- flash attention (split-3 bf16, 64-row Q tiles) ----------------
#define LDQ 72
#define FA_TILE (64 * LDQ)
#define FA_SMEM (6 * FA_TILE * 2)
__global__ void __launch_bounds__(128)
flash_kernel(const __nv_bfloat16* __restrict__ qkvh,
             const __nv_bfloat16* __restrict__ qkvl,
             __half* __restrict__ oh, __half* __restrict__ ol)
{
    extern __shared__ __nv_bfloat16 smem[];
    __nv_bfloat16* Qh = smem;
    __nv_bfloat16* Ql = Qh + FA_TILE;
    __nv_bfloat16* Kh = Ql + FA_TILE;
    __nv_bfloat16* Kl = Kh + FA_TILE;
    __nv_bfloat16* Vh = Kl + FA_TILE;
    __nv_bfloat16* Vl = Vh + FA_TILE;

    int it = (S_ / 64 - 1) - blockIdx.x;
    int z  = blockIdx.y;
    int b = z / H_, h = z % H_;
    int tid = threadIdx.x, lane = tid & 31, wm = tid >> 5;
    size_t rowbase = (size_t)b * S_;

    {
        size_t qoff = (rowbase + it * 64) * QKVN + h * D_;
        for (int cc = tid; cc < 512; cc += 128) {
            int r = cc >> 3, c = cc & 7;
            *(uint4*)&Qh[r * LDQ + c * 8] = *(const uint4*)(qkvh + qoff + (size_t)r * QKVN + c * 8);
            *(uint4*)&Ql[r * LDQ + c * 8] = *(const uint4*)(qkvl + qoff + (size_t)r * QKVN + c * 8);
        }
    }
    uint32_t qh_s = (uint32_t)__cvta_generic_to_shared(Qh);
    uint32_t ql_s = (uint32_t)__cvta_generic_to_shared(Ql);
    uint32_t kh_s = (uint32_t)__cvta_generic_to_shared(Kh);
    uint32_t kl_s = (uint32_t)__cvta_generic_to_shared(Kl);
    uint32_t vh_s = (uint32_t)__cvta_generic_to_shared(Vh);
    uint32_t vl_s = (uint32_t)__cvta_generic_to_shared(Vl);

    float oacc[8][4];
    #pragma unroll
    for (int j = 0; j < 8; ++j)
        #pragma unroll
        for (int t = 0; t < 4; ++t) oacc[j][t] = 0.f;
    float m_prev[2] = { -1e30f, -1e30f };
    float lsum[2]   = { 0.f, 0.f };

    for (int jt = 0; jt <= it; ++jt) {
        __syncthreads();
        size_t koff = (rowbase + jt * 64) * QKVN + E_ + h * D_;
        size_t voff = koff + E_;
        for (int cc = tid; cc < 512; cc += 128) {
            int r = cc >> 3, c = cc & 7;
            size_t gr = (size_t)r * QKVN + c * 8;
            int so = r * LDQ + c * 8;
            *(uint4*)&Kh[so] = *(const uint4*)(qkvh + koff + gr);
            *(uint4*)&Kl[so] = *(const uint4*)(qkvl + koff + gr);
            *(uint4*)&Vh[so] = *(const uint4*)(qkvh + voff + gr);
            *(uint4*)&Vl[so] = *(const uint4*)(qkvl + voff + gr);
        }
        __syncthreads();

        float sacc[8][4];
        #pragma unroll
        for (int j = 0; j < 8; ++j)
            #pragma unroll
            for (int t = 0; t < 4; ++t) sacc[j][t] = 0.f;

        #pragma unroll
        for (int kc = 0; kc < 4; ++kc) {
            uint32_t a_off = (uint32_t)((wm * 16 + (lane & 15)) * LDQ + kc * 16 + (lane >> 4) * 8) * 2;
            uint32_t afh[4], afl[4];
            ldm_x4(afh, qh_s + a_off);
            ldm_x4(afl, ql_s + a_off);
            #pragma unroll
            for (int np = 0; np < 4; ++np) {
                int nrow = np * 16 + (lane & 7) + ((lane >> 4) << 3);
                int ncol = kc * 16 + ((lane >> 3) & 1) * 8;
                uint32_t b_off = (uint32_t)(nrow * LDQ + ncol) * 2;
                uint32_t brh[4], brl[4];
                ldm_x4(brh, kh_s + b_off);
                ldm_x4(brl, kl_s + b_off);
                mma_bf16(sacc[np * 2],     afh, brh);
                mma_bf16(sacc[np * 2],     afh, brl);
                mma_bf16(sacc[np * 2],     afl, brh);
                mma_bf16(sacc[np * 2 + 1], afh, brh + 2);
                mma_bf16(sacc[np * 2 + 1], afh, brl + 2);
                mma_bf16(sacc[np * 2 + 1], afl, brh + 2);
            }
        }

        int rloc = wm * 16 + (lane >> 2);
        float mtile[2] = { -1e30f, -1e30f };
        bool diag = (jt == it);
        #pragma unroll
        for (int j = 0; j < 8; ++j) {
            int cg = jt * 64 + j * 8 + (lane & 3) * 2;
            #pragma unroll
            for (int rh = 0; rh < 2; ++rh) {
                int rg = it * 64 + rloc + rh * 8;
                float s0 = sacc[j][rh * 2]     * 0.125f;
                float s1 = sacc[j][rh * 2 + 1] * 0.125f;
                if (diag) {
                    if (cg     > rg) s0 = -1e30f;
                    if (cg + 1 > rg) s1 = -1e30f;
                }
                sacc[j][rh * 2]     = s0;
                sacc[j][rh * 2 + 1] = s1;
                mtile[rh] = fmaxf(mtile[rh], fmaxf(s0, s1));
            }
        }
        #pragma unroll
        for (int rh = 0; rh < 2; ++rh) {
            mtile[rh] = fmaxf(mtile[rh], __shfl_xor_sync(0xffffffff, mtile[rh], 1));
            mtile[rh] = fmaxf(mtile[rh], __shfl_xor_sync(0xffffffff, mtile[rh], 2));
        }
        float alpha[2];
        #pragma unroll
        for (int rh = 0; rh < 2; ++rh) {
            float mn = fmaxf(m_prev[rh], mtile[rh]);
            alpha[rh] = __expf(m_prev[rh] - mn);
            m_prev[rh] = mn;
        }
        float rsum[2] = { 0.f, 0.f };
        #pragma unroll
        for (int j = 0; j < 8; ++j)
            #pragma unroll
            for (int rh = 0; rh < 2; ++rh) {
                float p0 = __expf(sacc[j][rh * 2]     - m_prev[rh]);
                float p1 = __expf(sacc[j][rh * 2 + 1] - m_prev[rh]);
                sacc[j][rh * 2] = p0; sacc[j][rh * 2 + 1] = p1;
                rsum[rh] += p0 + p1;
            }
        #pragma unroll
        for (int rh = 0; rh < 2; ++rh) {
            rsum[rh] += __shfl_xor_sync(0xffffffff, rsum[rh], 1);
            rsum[rh] += __shfl_xor_sync(0xffffffff, rsum[rh], 2);
            lsum[rh] = lsum[rh] * alpha[rh] + rsum[rh];
        }
        #pragma unroll
        for (int j = 0; j < 8; ++j)
            #pragma unroll
            for (int rh = 0; rh < 2; ++rh) {
                oacc[j][rh * 2]     *= alpha[rh];
                oacc[j][rh * 2 + 1] *= alpha[rh];
            }
        #pragma unroll
        for (int kc = 0; kc < 4; ++kc) {
            uint32_t pah[4], pal[4];
            split_pack2_bf(sacc[2 * kc][0],     sacc[2 * kc][1],     pah[0], pal[0]);
            split_pack2_bf(sacc[2 * kc][2],     sacc[2 * kc][3],     pah[1], pal[1]);
            split_pack2_bf(sacc[2 * kc + 1][0], sacc[2 * kc + 1][1], pah[2], pal[2]);
            split_pack2_bf(sacc[2 * kc + 1][2], sacc[2 * kc + 1][3], pah[3], pal[3]);
            #pragma unroll
            for (int np = 0; np < 4; ++np) {
                int g = lane >> 3;
                int krow = kc * 16 + (g & 1) * 8 + (lane & 7);
                int ncol = np * 16 + (g >> 1) * 8;
                uint32_t v_off = (uint32_t)(krow * LDQ + ncol) * 2;
                uint32_t brh[4], brl[4];
                ldm_x4_trans(brh, vh_s + v_off);
                ldm_x4_trans(brl, vl_s + v_off);
                mma_bf16(oacc[np * 2],     pah, brh);
                mma_bf16(oacc[np * 2],     pah, brl);
                mma_bf16(oacc[np * 2],     pal, brh);
                mma_bf16(oacc[np * 2 + 1], pah, brh + 2);
                mma_bf16(oacc[np * 2 + 1], pah, brl + 2);
                mma_bf16(oacc[np * 2 + 1], pal, brh + 2);
            }
        }
    }

    float inv[2] = { 1.f / lsum[0], 1.f / lsum[1] };
    size_t gr0 = rowbase + it * 64 + wm * 16 + (lane >> 2);
    #pragma unroll
    for (int j = 0; j < 8; ++j) {
        int col = h * D_ + j * 8 + (lane & 3) * 2;
        #pragma unroll
        for (int rh = 0; rh < 2; ++rh) {
            size_t gr = gr0 + rh * 8;
            float v0 = oacc[j][rh * 2]     * inv[rh];
            float v1 = oacc[j][rh * 2 + 1] * inv[rh];
            split_write2_h(v0, v1, oh + gr * E_ + col, ol + gr * E_ + col);
        }
    }
}

// ---------------- host launcher ----------------
extern "C" void kernel_launch(void* const* d_in, const int* in_sizes, int n_in,
                              void* d_out, int out_size)
{
    const int*   tokens  = (const int*)  d_in[0];
    const float* tok_emb = (const float*)d_in[1];
    const float* pos_emb = (const float*)d_in[2];
    const float* Wq = (const float*)d_in[3];
    const float* bq = (const float*)d_in[4];
    const float* Wk = (const float*)d_in[5];
    const float* bk = (const float*)d_in[6];
    const float* Wv = (const float*)d_in[7];
    const float* bv = (const float*)d_in[8];
    const float* Wo = (const float*)d_in[9];
    const float* bo = (const float*)d_in[10];
    const float* ln1_g = (const float*)d_in[11];
    const float* ln1_b = (const float*)d_in[12];
    const float* ln2_g = (const float*)d_in[13];
    const float* ln2_b = (const float*)d_in[14];
    const float* W1 = (const float*)d_in[15];
    const float* b1 = (const float*)d_in[16];
    const float* W2 = (const float*)d_in[17];
    const float* b2 = (const float*)d_in[18];
    const float* lnf_g = (const float*)d_in[19];
    const float* lnf_b = (const float*)d_in[20];
    const float* Wf = (const float*)d_in[21];
    const float* bf = (const float*)d_in[22];
    float* out = (float*)d_out;

    float *x, *bqkv;
    __nv_bfloat16 *qkvh, *qkvl;
    __half *ahE, *alE, *ahF, *alF;
    __half *wqkv, *wo, *w1, *w2, *wf;
    cudaGetSymbolAddress((void**)&x,    g_x);
    cudaGetSymbolAddress((void**)&bqkv, g_bqkv);
    cudaGetSymbolAddress((void**)&qkvh, g_qkvh);
    cudaGetSymbolAddress((void**)&qkvl, g_qkvl);
    cudaGetSymbolAddress((void**)&ahE,  g_ahE);
    cudaGetSymbolAddress((void**)&alE,  g_alE);
    cudaGetSymbolAddress((void**)&ahF,  g_ahF);
    cudaGetSymbolAddress((void**)&alF,  g_alF);
    cudaGetSymbolAddress((void**)&wqkv, g_wqkv);
    cudaGetSymbolAddress((void**)&wo,   g_wo);
    cudaGetSymbolAddress((void**)&w1,   g_w1);
    cudaGetSymbolAddress((void**)&w2,   g_w2);
    cudaGetSymbolAddress((void**)&wf,   g_wf);

    const size_t EE = (size_t)E_ * E_;
    cudaFuncSetAttribute(flash_kernel, cudaFuncAttributeMaxDynamicSharedMemorySize, FA_SMEM);
    cudaFuncSetAttribute(bgemm2_kernel<2, 2, true, false, false>,
                         cudaFuncAttributeMaxDynamicSharedMemorySize, GSMEM);
    cudaFuncSetAttribute(bgemm2_kernel<2, 0, true, true, false>,
                         cudaFuncAttributeMaxDynamicSharedMemorySize, GSMEM);
    cudaFuncSetAttribute(bgemm2_kernel<2, 3, true, false, true>,
                         cudaFuncAttributeMaxDynamicSharedMemorySize, GSMEM);
    cudaFuncSetAttribute(bgemm2_kernel<1, 0, true, false, false>,
                         cudaFuncAttributeMaxDynamicSharedMemorySize, GSMEM);

    // ---- fused weight conversion (one launch) ----
    convert_all_kernel<<<4096, 256>>>(
        (const float4*)Wq, (const float4*)Wk, (const float4*)Wv, (const float4*)Wo,
        (const float4*)W1, (const float4*)W2, (const float4*)Wf,
        (uint2*)wqkv, (uint2*)wo, (uint2*)w1, (uint2*)w2, (uint2*)wf);
    concat_bias_kernel<<<(L_ * QKVN + 255) / 256, 256>>>(bq, bk, bv, bqkv);

    embed_kernel<<<M_, 192>>>(tokens, tok_emb, pos_emb, x);

    dim3 gQKV (M_ / 128, QKVN / 128);   // 16 x 18
    dim3 gProj(M_ / 128, E_ / 128);     // 16 x 6
    dim3 gFF1 (M_ / 128, FF_ / 128);    // 16 x 36
    dim3 gHead(M_ / 128, V_ / 128);     // 16 x 250
    dim3 gFA  (S_ / 64, B_ * H_);       // 16 x 24

    for (int l = 0; l < L_; ++l) {
        size_t qoff = (size_t)l * E_ * QKVN;
        size_t ooff = (size_t)l * EE;
        size_t f1 = (size_t)l * E_ * FF_;
        size_t f2 = (size_t)l * FF_ * E_;

        ln_split_kernel<<<M_, 256>>>(x, ln1_g + l * E_, ln1_b + l * E_, ahE, alE);

        // qkv = h @ Wqkv + b   -> bf16 split planes (2-term)
        bgemm2_kernel<2, 2, true, false, false><<<gQKV, 256, GSMEM>>>(
            ahE, alE, wqkv + qoff, bqkv + l * QKVN, nullptr,
            nullptr, qkvh, qkvl, nullptr, nullptr, QKVN, E_);

        flash_kernel<<<gFA, 128, FA_SMEM>>>(qkvh, qkvl, ahE, alE);

        // x = x + o @ Wo + bo   (2-term)
        bgemm2_kernel<2, 0, true, true, false><<<gProj, 256, GSMEM>>>(
            ahE, alE, wo + ooff, bo + l * E_, x,
            x, nullptr, nullptr, nullptr, nullptr, E_, E_);

        ln_split_kernel<<<M_, 256>>>(x, ln2_g + l * E_, ln2_b + l * E_, ahE, alE);

        // ff = gelu(h @ W1 + b1)  (2-term)
        bgemm2_kernel<2, 3, true, false, true><<<gFF1, 256, GSMEM>>>(
            ahE, alE, w1 + f1, b1 + l * FF_, nullptr,
            nullptr, nullptr, nullptr, ahF, alF, FF_, E_);

        // x = x + ff @ W2 + b2   (2-term)
        bgemm2_kernel<2, 0, true, true, false><<<gProj, 256, GSMEM>>>(
            ahF, alF, w2 + f2, b2 + l * E_, x,
            x, nullptr, nullptr, nullptr, nullptr, E_, FF_);
    }

    ln_split_kernel<<<M_, 256>>>(x, lnf_g, lnf_b, ahE, alE);
    // LM head: single-term fp16 (spends error budget; halves head FLOPs)
    bgemm2_kernel<1, 0, true, false, false><<<gHead, 256, GSMEM>>>(
        ahE, alE, wf, bf, nullptr,
        out, nullptr, nullptr, nullptr, nullptr, V_, E_);
}

// round 16
// speedup vs baseline: 1.4414x; 1.1919x over previous
#include <cuda_runtime.h>
#include <cuda_bf16.h>
#include <cuda_fp16.h>
#include <math.h>
#include <stdint.h>

// Problem dims (compile-time)
#define E_  768
#define H_  12
#define D_  64
#define L_  4
#define S_  1024
#define B_  2
#define V_  32000
#define FF_ 4608
#define M_  (B_ * S_)   // 2048 rows
#define QKVN 2304       // 3*E

// ---------------- scratch ----------------
__device__ float g_x[M_ * E_];
__device__ float g_bqkv[L_ * QKVN];
__device__ __half g_qkvh[(size_t)M_ * QKVN];   // qkv hi plane (fp16)
__device__ __half g_qkvl[(size_t)M_ * QKVN];   // qkv lo plane (fp16, used for Q only)
__device__ __half g_ahE[(size_t)M_ * E_];
__device__ __half g_alE[(size_t)M_ * E_];
__device__ __half g_ahF[(size_t)M_ * FF_];
__device__ __half g_wqkv[(size_t)L_ * E_ * QKVN];
__device__ __half g_wo  [(size_t)L_ * E_ * E_];
__device__ __half g_w1  [(size_t)L_ * E_ * FF_];
__device__ __half g_w2  [(size_t)L_ * FF_ * E_];
__device__ __half g_wf  [(size_t)E_ * V_];

// ---------------- small helpers ----------------
__device__ __forceinline__ void split_write2_h(float v0, float v1,
                                               __half* ph, __half* pl) {
    __half h0 = __float2half_rn(v0), h1 = __float2half_rn(v1);
    *(__half2*)ph = __halves2half2(h0, h1);
    *(__half2*)pl = __halves2half2(__float2half_rn(v0 - __half2float(h0)),
                                   __float2half_rn(v1 - __half2float(h1)));
}
__device__ __forceinline__ void split_pack2_h(float a, float b, uint32_t& hi, uint32_t& lo) {
    __half ha = __float2half_rn(a), hb = __float2half_rn(b);
    __half2 hh = __halves2half2(ha, hb);
    hi = *reinterpret_cast<uint32_t*>(&hh);
    __half2 ll = __halves2half2(__float2half_rn(a - __half2float(ha)),
                                __float2half_rn(b - __half2float(hb)));
    lo = *reinterpret_cast<uint32_t*>(&ll);
}

// ---------------- embedding ----------------
__global__ void embed_kernel(const int* __restrict__ tokens,
                             const float* __restrict__ tok_emb,
                             const float* __restrict__ pos_emb,
                             float* __restrict__ x)
{
    int row = blockIdx.x;
    int s   = row % S_;
    int t   = tokens[row];
    const float4* te = (const float4*)(tok_emb + (size_t)t * E_);
    const float4* pe = (const float4*)(pos_emb + (size_t)s * E_);
    float4*       xo = (float4*)(x + (size_t)row * E_);
    for (int i = threadIdx.x; i < E_ / 4; i += blockDim.x) {
        float4 a = te[i], b = pe[i];
        xo[i] = make_float4(a.x + b.x, a.y + b.y, a.z + b.z, a.w + b.w);
    }
}

// ---------------- layernorm -> fp16 split planes ----------------
__global__ void __launch_bounds__(256)
ln_split_kernel(const float* __restrict__ x,
                const float* __restrict__ g,
                const float* __restrict__ b,
                __half* __restrict__ oh,
                __half* __restrict__ ol)
{
    int row = blockIdx.x;
    int tid = threadIdx.x;
    __shared__ float red[256];
    const float4* xr4 = (const float4*)(x + (size_t)row * E_);

    float4 v = make_float4(0.f, 0.f, 0.f, 0.f);
    bool act = tid < E_ / 4;
    if (act) v = xr4[tid];

    float s = v.x + v.y + v.z + v.w;
    red[tid] = s; __syncthreads();
    for (int o = 128; o > 0; o >>= 1) { if (tid < o) red[tid] += red[tid + o]; __syncthreads(); }
    float mean = red[0] * (1.f / E_);
    __syncthreads();

    float sq = 0.f;
    if (act) {
        float d0 = v.x - mean, d1 = v.y - mean, d2 = v.z - mean, d3 = v.w - mean;
        sq = d0 * d0 + d1 * d1 + d2 * d2 + d3 * d3;
    }
    red[tid] = sq; __syncthreads();
    for (int o = 128; o > 0; o >>= 1) { if (tid < o) red[tid] += red[tid + o]; __syncthreads(); }
    float inv = rsqrtf(red[0] * (1.f / E_) + 1e-5f);

    if (act) {
        float4 g4 = ((const float4*)g)[tid];
        float4 b4 = ((const float4*)b)[tid];
        float y0 = (v.x - mean) * inv * g4.x + b4.x;
        float y1 = (v.y - mean) * inv * g4.y + b4.y;
        float y2 = (v.z - mean) * inv * g4.z + b4.z;
        float y3 = (v.w - mean) * inv * g4.w + b4.w;
        int col = tid * 4;
        __half* ohr = oh + (size_t)row * E_ + col;
        __half* olr = ol + (size_t)row * E_ + col;
        split_write2_h(y0, y1, ohr,     olr);
        split_write2_h(y2, y3, ohr + 2, olr + 2);
    }
}

// ---------------- fused weight conversion: all tensors, one launch ----------------
#define CS0 (L_ * E_ * E_ / 4)      // per tensor: Wq / Wk / Wv / Wo
#define CS1 (L_ * E_ * FF_ / 4)     // W1 / W2
#define CS2 (E_ * V_ / 4)           // Wf
#define CTOTAL (4 * CS0 + 2 * CS1 + CS2)
__global__ void convert_all_kernel(const float4* __restrict__ Wq4, const float4* __restrict__ Wk4,
                                   const float4* __restrict__ Wv4, const float4* __restrict__ Wo4,
                                   const float4* __restrict__ W14, const float4* __restrict__ W24,
                                   const float4* __restrict__ Wf4,
                                   uint2* __restrict__ wqkv_u, uint2* __restrict__ wo_u,
                                   uint2* __restrict__ w1_u, uint2* __restrict__ w2_u,
                                   uint2* __restrict__ wf_u)
{
    for (int idx = blockIdx.x * blockDim.x + threadIdx.x; idx < CTOTAL;
         idx += gridDim.x * blockDim.x) {
        float4 w;
        uint2* dst;
        if (idx < 3 * CS0) {                         // Q|K|V -> interleaved wqkv
            int which = idx / CS0;
            int r = idx - which * CS0;
            const float4* src = (which == 0) ? Wq4 : (which == 1) ? Wk4 : Wv4;
            w = src[r];
            int l  = r / (E_ * E_ / 4);
            int rr = r - l * (E_ * E_ / 4);
            int row = rr / (E_ / 4);
            int n4  = rr - row * (E_ / 4);
            dst = wqkv_u + ((size_t)l * E_ + row) * (QKVN / 4) + which * (E_ / 4) + n4;
        } else if (idx < 4 * CS0) {
            int r = idx - 3 * CS0;
            w = Wo4[r]; dst = wo_u + r;
        } else if (idx < 4 * CS0 + CS1) {
            int r = idx - 4 * CS0;
            w = W14[r]; dst = w1_u + r;
        } else if (idx < 4 * CS0 + 2 * CS1) {
            int r = idx - 4 * CS0 - CS1;
            w = W24[r]; dst = w2_u + r;
        } else {
            int r = idx - 4 * CS0 - 2 * CS1;
            w = Wf4[r]; dst = wf_u + r;
        }
        __half2 p0 = __floats2half2_rn(w.x, w.y);
        __half2 p1 = __floats2half2_rn(w.z, w.w);
        uint2 hv;
        hv.x = *reinterpret_cast<uint32_t*>(&p0);
        hv.y = *reinterpret_cast<uint32_t*>(&p1);
        *dst = hv;
    }
}

__global__ void concat_bias_kernel(const float* __restrict__ bq,
                                   const float* __restrict__ bk,
                                   const float* __restrict__ bv,
                                   float* __restrict__ bqkv)
{
    int t = blockIdx.x * blockDim.x + threadIdx.x;
    if (t >= L_ * QKVN) return;
    int l = t / QKVN, c = t - l * QKVN;
    float v;
    if (c < E_)           v = bq[l * E_ + c];
    else if (c < 2 * E_)  v = bk[l * E_ + c - E_];
    else                  v = bv[l * E_ + c - 2 * E_];
    bqkv[t] = v;
}

// ---------------- PTX helpers ----------------
__device__ __forceinline__ void cp_async16(uint32_t s, const void* g) {
    asm volatile("cp.async.cg.shared.global [%0], [%1], 16;" :: "r"(s), "l"(g));
}
__device__ __forceinline__ void cp_commit() {
    asm volatile("cp.async.commit_group;");
}
template<int N>
__device__ __forceinline__ void cp_wait() {
    asm volatile("cp.async.wait_group %0;" :: "n"(N));
}
__device__ __forceinline__ void ldm_x4(uint32_t* r, uint32_t addr) {
    asm volatile("ldmatrix.sync.aligned.m8n8.x4.shared.b16 {%0,%1,%2,%3}, [%4];"
                 : "=r"(r[0]), "=r"(r[1]), "=r"(r[2]), "=r"(r[3]) : "r"(addr));
}
__device__ __forceinline__ void ldm_x4_trans(uint32_t* r, uint32_t addr) {
    asm volatile("ldmatrix.sync.aligned.m8n8.x4.trans.shared.b16 {%0,%1,%2,%3}, [%4];"
                 : "=r"(r[0]), "=r"(r[1]), "=r"(r[2]), "=r"(r[3]) : "r"(addr));
}
__device__ __forceinline__ void mma_f16(float* d, const uint32_t* a, const uint32_t* b) {
    asm volatile(
        "mma.sync.aligned.m16n8k16.row.col.f32.f16.f16.f32 "
        "{%0,%1,%2,%3}, {%4,%5,%6,%7}, {%8,%9}, {%0,%1,%2,%3};"
        : "+f"(d[0]), "+f"(d[1]), "+f"(d[2]), "+f"(d[3])
        : "r"(a[0]), "r"(a[1]), "r"(a[2]), "r"(a[3]), "r"(b[0]), "r"(b[1]));
}

// ---------------- fp16 tensor-core GEMM, 4-stage cp.async pipeline ----------------
// TERMS=2: C = Ah@Bf + Al@Bf (A exact as fp16 pair).  TERMS=1: C = Ah@Bf.
// OUT: 0 = fp32 C (bias/res), 3 = fp16 split planes, 4 = fp16 single plane
#define GLDA 40
#define GLDB 136
#define GSTAGES 4
#define GABYTES (128 * GLDA * 2)
#define GBBYTES (32 * GLDB * 2)
#define GSMEM (GSTAGES * (GABYTES + GBBYTES))   // 75776 B
template<int TERMS, int OUT, bool BIAS, bool RES, bool GELU>
__global__ void __launch_bounds__(256)
bgemm2_kernel(const __half* __restrict__ Ah, const __half* __restrict__ Al,
              const __half* __restrict__ Bf,
              const float* __restrict__ bias, const float* __restrict__ res,
              float* __restrict__ Cf,
              __half* __restrict__ Chh, __half* __restrict__ Chl,
              int Nd, int Kd)
{
    extern __shared__ __half dsm[];

    int tid  = threadIdx.x;
    int lane = tid & 31, wid = tid >> 5;
    int wm = wid & 3, wn = wid >> 2;
    int row0 = blockIdx.x * 128, col0 = blockIdx.y * 128;

    uint32_t as0 = (uint32_t)__cvta_generic_to_shared(dsm);
    uint32_t bs0 = as0 + GSTAGES * GABYTES;

    float acc[2][8][4];
    #pragma unroll
    for (int i = 0; i < 2; ++i)
        #pragma unroll
        for (int j = 0; j < 8; ++j)
            #pragma unroll
            for (int t = 0; t < 4; ++t) acc[i][j][t] = 0.f;

    const int KSEG = Kd / 32;
    const int KT   = TERMS * KSEG;

    auto load_tile = [&](int buf, int kt) {
        int seg = (kt < KSEG) ? 0 : 1;
        const __half* Ab = seg ? Al : Ah;
        int k0 = (kt - seg * KSEG) * 32;
        uint32_t ab = as0 + buf * GABYTES;
        uint32_t bb = bs0 + buf * GBBYTES;
        #pragma unroll
        for (int i = 0; i < 2; ++i) {
            int chunk = tid * 2 + i;
            int m = chunk >> 2, c = chunk & 3;
            const void* g = Ab + (size_t)(row0 + m) * Kd + k0 + c * 8;
            cp_async16(ab + (uint32_t)(m * GLDA + c * 8) * 2, g);
        }
        #pragma unroll
        for (int i = 0; i < 2; ++i) {
            int chunk = tid * 2 + i;
            int k = chunk >> 4, c = chunk & 15;
            const void* g = Bf + (size_t)(k0 + k) * Nd + col0 + c * 8;
            cp_async16(bb + (uint32_t)(k * GLDB + c * 8) * 2, g);
        }
    };

    #pragma unroll
    for (int p = 0; p < GSTAGES - 1; ++p) {
        if (p < KT) load_tile(p, p);
        cp_commit();
    }

    for (int kt = 0; kt < KT; ++kt) {
        cp_wait<GSTAGES - 2>();
        __syncthreads();
        int buf = kt & (GSTAGES - 1);
        uint32_t ab = as0 + buf * GABYTES;
        uint32_t bb = bs0 + buf * GBBYTES;

        #pragma unroll
        for (int kk = 0; kk < 2; ++kk) {
            uint32_t af[2][4];
            #pragma unroll
            for (int mi = 0; mi < 2; ++mi) {
                int m  = wm * 32 + mi * 16 + (lane & 15);
                int kc = kk * 16 + (lane >> 4) * 8;
                ldm_x4(af[mi], ab + (uint32_t)(m * GLDA + kc) * 2);
            }
            uint32_t bfrag[8][2];
            #pragma unroll
            for (int ni4 = 0; ni4 < 4; ++ni4) {
                int g    = lane >> 3;
                int krow = kk * 16 + (g & 1) * 8 + (lane & 7);
                int ncol = wn * 64 + ni4 * 16 + (g >> 1) * 8;
                uint32_t r[4];
                ldm_x4_trans(r, bb + (uint32_t)(krow * GLDB + ncol) * 2);
                bfrag[2 * ni4][0] = r[0]; bfrag[2 * ni4][1] = r[1];
                bfrag[2 * ni4 + 1][0] = r[2]; bfrag[2 * ni4 + 1][1] = r[3];
            }
            #pragma unroll
            for (int mi = 0; mi < 2; ++mi)
                #pragma unroll
                for (int ni = 0; ni < 8; ++ni)
                    mma_f16(acc[mi][ni], af[mi], bfrag[ni]);
        }

        int nx = kt + GSTAGES - 1;
        if (nx < KT) load_tile(nx & (GSTAGES - 1), nx);
        cp_commit();
    }

    // epilogue
    #pragma unroll
    for (int mi = 0; mi < 2; ++mi) {
        int r = row0 + wm * 32 + mi * 16 + (lane >> 2);
        #pragma unroll
        for (int ni = 0; ni < 8; ++ni) {
            int c = col0 + wn * 64 + ni * 8 + (lane & 3) * 2;
            float b0 = 0.f, b1 = 0.f;
            if (BIAS) { b0 = bias[c]; b1 = bias[c + 1]; }
            #pragma unroll
            for (int half = 0; half < 2; ++half) {
                int rr = r + half * 8;
                float v0 = acc[mi][ni][half * 2 + 0] + b0;
                float v1 = acc[mi][ni][half * 2 + 1] + b1;
                if (GELU) {
                    v0 = 0.5f * v0 * (1.f + erff(v0 * 0.70710678118654752f));
                    v1 = 0.5f * v1 * (1.f + erff(v1 * 0.70710678118654752f));
                }
                if (RES) {
                    const float2 rv = *(const float2*)(res + (size_t)rr * Nd + c);
                    v0 += rv.x; v1 += rv.y;
                }
                if (OUT == 0) {
                    *(float2*)(Cf + (size_t)rr * Nd + c) = make_float2(v0, v1);
                } else if (OUT == 3) {
                    split_write2_h(v0, v1, Chh + (size_t)rr * Nd + c, Chl + (size_t)rr * Nd + c);
                } else {   // OUT == 4
                    __half2 hv = __halves2half2(__float2half_rn(v0), __float2half_rn(v1));
                    *(__half2*)(Chh + (size_t)rr * Nd + c) = hv;
                }
            }
        }
    }
}

// ---------------- flash attention (fp16 2-term, 64-row Q tiles) ----------------
// qkvh/qkvl: [M, 2304] fp16 planes.  Q exact as (Qh,Ql); K,V single-rounded (hi).
// S = Qh K^T + Ql K^T; O += Ph V + Pl V.
#define LDQ 72
#define FA_TILE (64 * LDQ)
#define FA_SMEM (4 * FA_TILE * 2)   // 36864 B
__global__ void __launch_bounds__(128)
flash_kernel(const __half* __restrict__ qkvh,
             const __half* __restrict__ qkvl,
             __half* __restrict__ oh, __half* __restrict__ ol)
{
    extern __shared__ __half fsm[];
    __half* Qh = fsm;
    __half* Ql = Qh + FA_TILE;
    __half* Kh = Ql + FA_TILE;
    __half* Vh = Kh + FA_TILE;

    int it = (S_ / 64 - 1) - blockIdx.x;   // heavy causal tiles first
    int z  = blockIdx.y;
    int b = z / H_, h = z % H_;
    int tid = threadIdx.x, lane = tid & 31, wm = tid >> 5;
    size_t rowbase = (size_t)b * S_;

    {
        size_t qoff = (rowbase + it * 64) * QKVN + h * D_;
        for (int cc = tid; cc < 512; cc += 128) {
            int r = cc >> 3, c = cc & 7;
            *(uint4*)&Qh[r * LDQ + c * 8] = *(const uint4*)(qkvh + qoff + (size_t)r * QKVN + c * 8);
            *(uint4*)&Ql[r * LDQ + c * 8] = *(const uint4*)(qkvl + qoff + (size_t)r * QKVN + c * 8);
        }
    }
    uint32_t qh_s = (uint32_t)__cvta_generic_to_shared(Qh);
    uint32_t ql_s = (uint32_t)__cvta_generic_to_shared(Ql);
    uint32_t kh_s = (uint32_t)__cvta_generic_to_shared(Kh);
    uint32_t vh_s = (uint32_t)__cvta_generic_to_shared(Vh);

    float oacc[8][4];
    #pragma unroll
    for (int j = 0; j < 8; ++j)
        #pragma unroll
        for (int t = 0; t < 4; ++t) oacc[j][t] = 0.f;
    float m_prev[2] = { -1e30f, -1e30f };
    float lsum[2]   = { 0.f, 0.f };

    for (int jt = 0; jt <= it; ++jt) {
        __syncthreads();
        size_t koff = (rowbase + jt * 64) * QKVN + E_ + h * D_;
        size_t voff = koff + E_;
        for (int cc = tid; cc < 512; cc += 128) {
            int r = cc >> 3, c = cc & 7;
            size_t gr = (size_t)r * QKVN + c * 8;
            int so = r * LDQ + c * 8;
            *(uint4*)&Kh[so] = *(const uint4*)(qkvh + koff + gr);
            *(uint4*)&Vh[so] = *(const uint4*)(qkvh + voff + gr);
        }
        __syncthreads();

        float sacc[8][4];
        #pragma unroll
        for (int j = 0; j < 8; ++j)
            #pragma unroll
            for (int t = 0; t < 4; ++t) sacc[j][t] = 0.f;

        // S = Qh K + Ql K
        #pragma unroll
        for (int kc = 0; kc < 4; ++kc) {
            uint32_t a_off = (uint32_t)((wm * 16 + (lane & 15)) * LDQ + kc * 16 + (lane >> 4) * 8) * 2;
            uint32_t afh[4], afl[4];
            ldm_x4(afh, qh_s + a_off);
            ldm_x4(afl, ql_s + a_off);
            #pragma unroll
            for (int np = 0; np < 4; ++np) {
                int nrow = np * 16 + (lane & 7) + ((lane >> 4) << 3);
                int ncol = kc * 16 + ((lane >> 3) & 1) * 8;
                uint32_t b_off = (uint32_t)(nrow * LDQ + ncol) * 2;
                uint32_t brh[4];
                ldm_x4(brh, kh_s + b_off);
                mma_f16(sacc[np * 2],     afh, brh);
                mma_f16(sacc[np * 2],     afl, brh);
                mma_f16(sacc[np * 2 + 1], afh, brh + 2);
                mma_f16(sacc[np * 2 + 1], afl, brh + 2);
            }
        }

        int rloc = wm * 16 + (lane >> 2);
        float mtile[2] = { -1e30f, -1e30f };
        bool diag = (jt == it);
        #pragma unroll
        for (int j = 0; j < 8; ++j) {
            int cg = jt * 64 + j * 8 + (lane & 3) * 2;
            #pragma unroll
            for (int rh = 0; rh < 2; ++rh) {
                int rg = it * 64 + rloc + rh * 8;
                float s0 = sacc[j][rh * 2]     * 0.125f;
                float s1 = sacc[j][rh * 2 + 1] * 0.125f;
                if (diag) {
                    if (cg     > rg) s0 = -1e30f;
                    if (cg + 1 > rg) s1 = -1e30f;
                }
                sacc[j][rh * 2]     = s0;
                sacc[j][rh * 2 + 1] = s1;
                mtile[rh] = fmaxf(mtile[rh], fmaxf(s0, s1));
            }
        }
        #pragma unroll
        for (int rh = 0; rh < 2; ++rh) {
            mtile[rh] = fmaxf(mtile[rh], __shfl_xor_sync(0xffffffff, mtile[rh], 1));
            mtile[rh] = fmaxf(mtile[rh], __shfl_xor_sync(0xffffffff, mtile[rh], 2));
        }
        float alpha[2];
        #pragma unroll
        for (int rh = 0; rh < 2; ++rh) {
            float mn = fmaxf(m_prev[rh], mtile[rh]);
            alpha[rh] = __expf(m_prev[rh] - mn);
            m_prev[rh] = mn;
        }
        float rsum[2] = { 0.f, 0.f };
        #pragma unroll
        for (int j = 0; j < 8; ++j)
            #pragma unroll
            for (int rh = 0; rh < 2; ++rh) {
                float p0 = __expf(sacc[j][rh * 2]     - m_prev[rh]);
                float p1 = __expf(sacc[j][rh * 2 + 1] - m_prev[rh]);
                sacc[j][rh * 2] = p0; sacc[j][rh * 2 + 1] = p1;
                rsum[rh] += p0 + p1;
            }
        #pragma unroll
        for (int rh = 0; rh < 2; ++rh) {
            rsum[rh] += __shfl_xor_sync(0xffffffff, rsum[rh], 1);
            rsum[rh] += __shfl_xor_sync(0xffffffff, rsum[rh], 2);
            lsum[rh] = lsum[rh] * alpha[rh] + rsum[rh];
        }
        #pragma unroll
        for (int j = 0; j < 8; ++j)
            #pragma unroll
            for (int rh = 0; rh < 2; ++rh) {
                oacc[j][rh * 2]     *= alpha[rh];
                oacc[j][rh * 2 + 1] *= alpha[rh];
            }
        // O += Ph V + Pl V
        #pragma unroll
        for (int kc = 0; kc < 4; ++kc) {
            uint32_t pah[4], pal[4];
            split_pack2_h(sacc[2 * kc][0],     sacc[2 * kc][1],     pah[0], pal[0]);
            split_pack2_h(sacc[2 * kc][2],     sacc[2 * kc][3],     pah[1], pal[1]);
            split_pack2_h(sacc[2 * kc + 1][0], sacc[2 * kc + 1][1], pah[2], pal[2]);
            split_pack2_h(sacc[2 * kc + 1][2], sacc[2 * kc + 1][3], pah[3], pal[3]);
            #pragma unroll
            for (int np = 0; np < 4; ++np) {
                int g = lane >> 3;
                int krow = kc * 16 + (g & 1) * 8 + (lane & 7);
                int ncol = np * 16 + (g >> 1) * 8;
                uint32_t v_off = (uint32_t)(krow * LDQ + ncol) * 2;
                uint32_t brh[4];
                ldm_x4_trans(brh, vh_s + v_off);
                mma_f16(oacc[np * 2],     pah, brh);
                mma_f16(oacc[np * 2],     pal, brh);
                mma_f16(oacc[np * 2 + 1], pah, brh + 2);
                mma_f16(oacc[np * 2 + 1], pal, brh + 2);
            }
        }
    }

    float inv[2] = { 1.f / lsum[0], 1.f / lsum[1] };
    size_t gr0 = rowbase + it * 64 + wm * 16 + (lane >> 2);
    #pragma unroll
    for (int j = 0; j < 8; ++j) {
        int col = h * D_ + j * 8 + (lane & 3) * 2;
        #pragma unroll
        for (int rh = 0; rh < 2; ++rh) {
            size_t gr = gr0 + rh * 8;
            float v0 = oacc[j][rh * 2]     * inv[rh];
            float v1 = oacc[j][rh * 2 + 1] * inv[rh];
            split_write2_h(v0, v1, oh + gr * E_ + col, ol + gr * E_ + col);
        }
    }
}

// ---------------- host launcher ----------------
extern "C" void kernel_launch(void* const* d_in, const int* in_sizes, int n_in,
                              void* d_out, int out_size)
{
    const int*   tokens  = (const int*)  d_in[0];
    const float* tok_emb = (const float*)d_in[1];
    const float* pos_emb = (const float*)d_in[2];
    const float* Wq = (const float*)d_in[3];
    const float* bq = (const float*)d_in[4];
    const float* Wk = (const float*)d_in[5];
    const float* bk = (const float*)d_in[6];
    const float* Wv = (const float*)d_in[7];
    const float* bv = (const float*)d_in[8];
    const float* Wo = (const float*)d_in[9];
    const float* bo = (const float*)d_in[10];
    const float* ln1_g = (const float*)d_in[11];
    const float* ln1_b = (const float*)d_in[12];
    const float* ln2_g = (const float*)d_in[13];
    const float* ln2_b = (const float*)d_in[14];
    const float* W1 = (const float*)d_in[15];
    const float* b1 = (const float*)d_in[16];
    const float* W2 = (const float*)d_in[17];
    const float* b2 = (const float*)d_in[18];
    const float* lnf_g = (const float*)d_in[19];
    const float* lnf_b = (const float*)d_in[20];
    const float* Wf = (const float*)d_in[21];
    const float* bf = (const float*)d_in[22];
    float* out = (float*)d_out;

    float *x, *bqkv;
    __half *qkvh, *qkvl;
    __half *ahE, *alE, *ahF;
    __half *wqkv, *wo, *w1, *w2, *wf;
    cudaGetSymbolAddress((void**)&x,    g_x);
    cudaGetSymbolAddress((void**)&bqkv, g_bqkv);
    cudaGetSymbolAddress((void**)&qkvh, g_qkvh);
    cudaGetSymbolAddress((void**)&qkvl, g_qkvl);
    cudaGetSymbolAddress((void**)&ahE,  g_ahE);
    cudaGetSymbolAddress((void**)&alE,  g_alE);
    cudaGetSymbolAddress((void**)&ahF,  g_ahF);
    cudaGetSymbolAddress((void**)&wqkv, g_wqkv);
    cudaGetSymbolAddress((void**)&wo,   g_wo);
    cudaGetSymbolAddress((void**)&w1,   g_w1);
    cudaGetSymbolAddress((void**)&w2,   g_w2);
    cudaGetSymbolAddress((void**)&wf,   g_wf);

    const size_t EE = (size_t)E_ * E_;
    cudaFuncSetAttribute(flash_kernel, cudaFuncAttributeMaxDynamicSharedMemorySize, FA_SMEM);
    cudaFuncSetAttribute(bgemm2_kernel<2, 3, true, false, false>,
                         cudaFuncAttributeMaxDynamicSharedMemorySize, GSMEM);
    cudaFuncSetAttribute(bgemm2_kernel<2, 0, true, true, false>,
                         cudaFuncAttributeMaxDynamicSharedMemorySize, GSMEM);
    cudaFuncSetAttribute(bgemm2_kernel<2, 4, true, false, true>,
                         cudaFuncAttributeMaxDynamicSharedMemorySize, GSMEM);
    cudaFuncSetAttribute(bgemm2_kernel<1, 0, true, true, false>,
                         cudaFuncAttributeMaxDynamicSharedMemorySize, GSMEM);
    cudaFuncSetAttribute(bgemm2_kernel<1, 0, true, false, false>,
                         cudaFuncAttributeMaxDynamicSharedMemorySize, GSMEM);

    // ---- fused weight conversion (one launch) ----
    convert_all_kernel<<<4096, 256>>>(
        (const float4*)Wq, (const float4*)Wk, (const float4*)Wv, (const float4*)Wo,
        (const float4*)W1, (const float4*)W2, (const float4*)Wf,
        (uint2*)wqkv, (uint2*)wo, (uint2*)w1, (uint2*)w2, (uint2*)wf);
    concat_bias_kernel<<<(L_ * QKVN + 255) / 256, 256>>>(bq, bk, bv, bqkv);

    embed_kernel<<<M_, 192>>>(tokens, tok_emb, pos_emb, x);

    dim3 gQKV (M_ / 128, QKVN / 128);   // 16 x 18
    dim3 gProj(M_ / 128, E_ / 128);     // 16 x 6
    dim3 gFF1 (M_ / 128, FF_ / 128);    // 16 x 36
    dim3 gHead(M_ / 128, V_ / 128);     // 16 x 250
    dim3 gFA  (S_ / 64, B_ * H_);       // 16 x 24

    for (int l = 0; l < L_; ++l) {
        size_t qoff = (size_t)l * E_ * QKVN;
        size_t ooff = (size_t)l * EE;
        size_t f1 = (size_t)l * E_ * FF_;
        size_t f2 = (size_t)l * FF_ * E_;

        ln_split_kernel<<<M_, 256>>>(x, ln1_g + l * E_, ln1_b + l * E_, ahE, alE);

        // qkv = h @ Wqkv + b   -> fp16 split planes (2-term)
        bgemm2_kernel<2, 3, true, false, false><<<gQKV, 256, GSMEM>>>(
            ahE, alE, wqkv + qoff, bqkv + l * QKVN, nullptr,
            nullptr, qkvh, qkvl, QKVN, E_);

        flash_kernel<<<gFA, 128, FA_SMEM>>>(qkvh, qkvl, ahE, alE);

        // x = x + o @ Wo + bo   (2-term)
        bgemm2_kernel<2, 0, true, true, false><<<gProj, 256, GSMEM>>>(
            ahE, alE, wo + ooff, bo + l * E_, x,
            x, nullptr, nullptr, E_, E_);

        ln_split_kernel<<<M_, 256>>>(x, ln2_g + l * E_, ln2_b + l * E_, ahE, alE);

        // ff = gelu(h @ W1 + b1)  (2-term, single fp16 output plane)
        bgemm2_kernel<2, 4, true, false, true><<<gFF1, 256, GSMEM>>>(
            ahE, alE, w1 + f1, b1 + l * FF_, nullptr,
            nullptr, ahF, nullptr, FF_, E_);

        // x = x + ff @ W2 + b2   (1-term: ff single-rounded)
        bgemm2_kernel<1, 0, true, true, false><<<gProj, 256, GSMEM>>>(
            ahF, ahF, w2 + f2, b2 + l * E_, x,
            x, nullptr, nullptr, E_, FF_);
    }

    ln_split_kernel<<<M_, 256>>>(x, lnf_g, lnf_b, ahE, alE);
    // LM head: single-term fp16
    bgemm2_kernel<1, 0, true, false, false><<<gHead, 256, GSMEM>>>(
        ahE, alE, wf, bf, nullptr,
        out, nullptr, nullptr, V_, E_);
}

// round 17
// speedup vs baseline: 1.6568x; 1.1494x over previous
#include <cuda_runtime.h>
#include <cuda_bf16.h>
#include <cuda_fp16.h>
#include <math.h>
#include <stdint.h>

// Problem dims (compile-time)
#define E_  768
#define H_  12
#define D_  64
#define L_  4
#define S_  1024
#define B_  2
#define V_  32000
#define FF_ 4608
#define M_  (B_ * S_)   // 2048 rows
#define QKVN 2304       // 3*E

// ---------------- scratch ----------------
__device__ float g_x[M_ * E_];
__device__ float g_bqkv[L_ * QKVN];
__device__ __half g_qkvh[(size_t)M_ * QKVN];   // qkv hi plane (fp16)
__device__ __half g_qkvl[(size_t)M_ * QKVN];   // qkv lo plane (fp16, used for Q only)
__device__ __half g_ahE[(size_t)M_ * E_];
__device__ __half g_alE[(size_t)M_ * E_];
__device__ __half g_ahF[(size_t)M_ * FF_];
__device__ __half g_wqkv[(size_t)L_ * E_ * QKVN];
__device__ __half g_wo  [(size_t)L_ * E_ * E_];
__device__ __half g_w1  [(size_t)L_ * E_ * FF_];
__device__ __half g_w2  [(size_t)L_ * FF_ * E_];
__device__ __half g_wf  [(size_t)E_ * V_];

// ---------------- small helpers ----------------
__device__ __forceinline__ void split_write2_h(float v0, float v1,
                                               __half* ph, __half* pl) {
    __half h0 = __float2half_rn(v0), h1 = __float2half_rn(v1);
    *(__half2*)ph = __halves2half2(h0, h1);
    *(__half2*)pl = __halves2half2(__float2half_rn(v0 - __half2float(h0)),
                                   __float2half_rn(v1 - __half2float(h1)));
}
__device__ __forceinline__ void split_pack2_h(float a, float b, uint32_t& hi, uint32_t& lo) {
    __half ha = __float2half_rn(a), hb = __float2half_rn(b);
    __half2 hh = __halves2half2(ha, hb);
    hi = *reinterpret_cast<uint32_t*>(&hh);
    __half2 ll = __halves2half2(__float2half_rn(a - __half2float(ha)),
                                __float2half_rn(b - __half2float(hb)));
    lo = *reinterpret_cast<uint32_t*>(&ll);
}

// ---------------- embedding ----------------
__global__ void embed_kernel(const int* __restrict__ tokens,
                             const float* __restrict__ tok_emb,
                             const float* __restrict__ pos_emb,
                             float* __restrict__ x)
{
    int row = blockIdx.x;
    int s   = row % S_;
    int t   = tokens[row];
    const float4* te = (const float4*)(tok_emb + (size_t)t * E_);
    const float4* pe = (const float4*)(pos_emb + (size_t)s * E_);
    float4*       xo = (float4*)(x + (size_t)row * E_);
    for (int i = threadIdx.x; i < E_ / 4; i += blockDim.x) {
        float4 a = te[i], b = pe[i];
        xo[i] = make_float4(a.x + b.x, a.y + b.y, a.z + b.z, a.w + b.w);
    }
}

// ---------------- layernorm -> single fp16 plane ----------------
__global__ void __launch_bounds__(256)
ln_h_kernel(const float* __restrict__ x,
            const float* __restrict__ g,
            const float* __restrict__ b,
            __half* __restrict__ oh)
{
    int row = blockIdx.x;
    int tid = threadIdx.x;
    __shared__ float red[256];
    const float4* xr4 = (const float4*)(x + (size_t)row * E_);

    float4 v = make_float4(0.f, 0.f, 0.f, 0.f);
    bool act = tid < E_ / 4;
    if (act) v = xr4[tid];

    float s = v.x + v.y + v.z + v.w;
    red[tid] = s; __syncthreads();
    for (int o = 128; o > 0; o >>= 1) { if (tid < o) red[tid] += red[tid + o]; __syncthreads(); }
    float mean = red[0] * (1.f / E_);
    __syncthreads();

    float sq = 0.f;
    if (act) {
        float d0 = v.x - mean, d1 = v.y - mean, d2 = v.z - mean, d3 = v.w - mean;
        sq = d0 * d0 + d1 * d1 + d2 * d2 + d3 * d3;
    }
    red[tid] = sq; __syncthreads();
    for (int o = 128; o > 0; o >>= 1) { if (tid < o) red[tid] += red[tid + o]; __syncthreads(); }
    float inv = rsqrtf(red[0] * (1.f / E_) + 1e-5f);

    if (act) {
        float4 g4 = ((const float4*)g)[tid];
        float4 b4 = ((const float4*)b)[tid];
        float y0 = (v.x - mean) * inv * g4.x + b4.x;
        float y1 = (v.y - mean) * inv * g4.y + b4.y;
        float y2 = (v.z - mean) * inv * g4.z + b4.z;
        float y3 = (v.w - mean) * inv * g4.w + b4.w;
        __half2 h01 = __halves2half2(__float2half_rn(y0), __float2half_rn(y1));
        __half2 h23 = __halves2half2(__float2half_rn(y2), __float2half_rn(y3));
        __half* ohr = oh + (size_t)row * E_ + tid * 4;
        *(__half2*)(ohr)     = h01;
        *(__half2*)(ohr + 2) = h23;
    }
}

// ---------------- fused weight conversion: all tensors, one launch ----------------
#define CS0 (L_ * E_ * E_ / 4)      // per tensor: Wq / Wk / Wv / Wo
#define CS1 (L_ * E_ * FF_ / 4)     // W1 / W2
#define CS2 (E_ * V_ / 4)           // Wf
#define CTOTAL (4 * CS0 + 2 * CS1 + CS2)
__global__ void convert_all_kernel(const float4* __restrict__ Wq4, const float4* __restrict__ Wk4,
                                   const float4* __restrict__ Wv4, const float4* __restrict__ Wo4,
                                   const float4* __restrict__ W14, const float4* __restrict__ W24,
                                   const float4* __restrict__ Wf4,
                                   uint2* __restrict__ wqkv_u, uint2* __restrict__ wo_u,
                                   uint2* __restrict__ w1_u, uint2* __restrict__ w2_u,
                                   uint2* __restrict__ wf_u)
{
    for (int idx = blockIdx.x * blockDim.x + threadIdx.x; idx < CTOTAL;
         idx += gridDim.x * blockDim.x) {
        float4 w;
        uint2* dst;
        if (idx < 3 * CS0) {                         // Q|K|V -> interleaved wqkv
            int which = idx / CS0;
            int r = idx - which * CS0;
            const float4* src = (which == 0) ? Wq4 : (which == 1) ? Wk4 : Wv4;
            w = src[r];
            int l  = r / (E_ * E_ / 4);
            int rr = r - l * (E_ * E_ / 4);
            int row = rr / (E_ / 4);
            int n4  = rr - row * (E_ / 4);
            dst = wqkv_u + ((size_t)l * E_ + row) * (QKVN / 4) + which * (E_ / 4) + n4;
        } else if (idx < 4 * CS0) {
            int r = idx - 3 * CS0;
            w = Wo4[r]; dst = wo_u + r;
        } else if (idx < 4 * CS0 + CS1) {
            int r = idx - 4 * CS0;
            w = W14[r]; dst = w1_u + r;
        } else if (idx < 4 * CS0 + 2 * CS1) {
            int r = idx - 4 * CS0 - CS1;
            w = W24[r]; dst = w2_u + r;
        } else {
            int r = idx - 4 * CS0 - 2 * CS1;
            w = Wf4[r]; dst = wf_u + r;
        }
        __half2 p0 = __floats2half2_rn(w.x, w.y);
        __half2 p1 = __floats2half2_rn(w.z, w.w);
        uint2 hv;
        hv.x = *reinterpret_cast<uint32_t*>(&p0);
        hv.y = *reinterpret_cast<uint32_t*>(&p1);
        *dst = hv;
    }
}

__global__ void concat_bias_kernel(const float* __restrict__ bq,
                                   const float* __restrict__ bk,
                                   const float* __restrict__ bv,
                                   float* __restrict__ bqkv)
{
    int t = blockIdx.x * blockDim.x + threadIdx.x;
    if (t >= L_ * QKVN) return;
    int l = t / QKVN, c = t - l * QKVN;
    float v;
    if (c < E_)           v = bq[l * E_ + c];
    else if (c < 2 * E_)  v = bk[l * E_ + c - E_];
    else                  v = bv[l * E_ + c - 2 * E_];
    bqkv[t] = v;
}

// ---------------- PTX helpers ----------------
__device__ __forceinline__ void cp_async16(uint32_t s, const void* g) {
    asm volatile("cp.async.cg.shared.global [%0], [%1], 16;" :: "r"(s), "l"(g));
}
__device__ __forceinline__ void cp_commit() {
    asm volatile("cp.async.commit_group;");
}
template<int N>
__device__ __forceinline__ void cp_wait() {
    asm volatile("cp.async.wait_group %0;" :: "n"(N));
}
__device__ __forceinline__ void ldm_x4(uint32_t* r, uint32_t addr) {
    asm volatile("ldmatrix.sync.aligned.m8n8.x4.shared.b16 {%0,%1,%2,%3}, [%4];"
                 : "=r"(r[0]), "=r"(r[1]), "=r"(r[2]), "=r"(r[3]) : "r"(addr));
}
__device__ __forceinline__ void ldm_x4_trans(uint32_t* r, uint32_t addr) {
    asm volatile("ldmatrix.sync.aligned.m8n8.x4.trans.shared.b16 {%0,%1,%2,%3}, [%4];"
                 : "=r"(r[0]), "=r"(r[1]), "=r"(r[2]), "=r"(r[3]) : "r"(addr));
}
__device__ __forceinline__ void mma_f16(float* d, const uint32_t* a, const uint32_t* b) {
    asm volatile(
        "mma.sync.aligned.m16n8k16.row.col.f32.f16.f16.f32 "
        "{%0,%1,%2,%3}, {%4,%5,%6,%7}, {%8,%9}, {%0,%1,%2,%3};"
        : "+f"(d[0]), "+f"(d[1]), "+f"(d[2]), "+f"(d[3])
        : "r"(a[0]), "r"(a[1]), "r"(a[2]), "r"(a[3]), "r"(b[0]), "r"(b[1]));
}

// ---------------- fp16 tensor-core GEMM, 4-stage cp.async pipeline ----------------
// TERMS=2: C = Ah@Bf + Al@Bf (A exact as fp16 pair).  TERMS=1: C = Ah@Bf.
// OUT: 0 = fp32 C (bias/res), 3 = fp16 split planes, 4 = fp16 single plane
#define GLDA 40
#define GLDB 136
#define GSTAGES 4
#define GABYTES (128 * GLDA * 2)
#define GBBYTES (32 * GLDB * 2)
#define GSMEM (GSTAGES * (GABYTES + GBBYTES))   // 75776 B
template<int TERMS, int OUT, bool BIAS, bool RES, bool GELU>
__global__ void __launch_bounds__(256)
bgemm2_kernel(const __half* __restrict__ Ah, const __half* __restrict__ Al,
              const __half* __restrict__ Bf,
              const float* __restrict__ bias, const float* __restrict__ res,
              float* __restrict__ Cf,
              __half* __restrict__ Chh, __half* __restrict__ Chl,
              int Nd, int Kd)
{
    extern __shared__ __half dsm[];

    int tid  = threadIdx.x;
    int lane = tid & 31, wid = tid >> 5;
    int wm = wid & 3, wn = wid >> 2;
    int row0 = blockIdx.x * 128, col0 = blockIdx.y * 128;

    uint32_t as0 = (uint32_t)__cvta_generic_to_shared(dsm);
    uint32_t bs0 = as0 + GSTAGES * GABYTES;

    float acc[2][8][4];
    #pragma unroll
    for (int i = 0; i < 2; ++i)
        #pragma unroll
        for (int j = 0; j < 8; ++j)
            #pragma unroll
            for (int t = 0; t < 4; ++t) acc[i][j][t] = 0.f;

    const int KSEG = Kd / 32;
    const int KT   = TERMS * KSEG;

    auto load_tile = [&](int buf, int kt) {
        int seg = (kt < KSEG) ? 0 : 1;
        const __half* Ab = seg ? Al : Ah;
        int k0 = (kt - seg * KSEG) * 32;
        uint32_t ab = as0 + buf * GABYTES;
        uint32_t bb = bs0 + buf * GBBYTES;
        #pragma unroll
        for (int i = 0; i < 2; ++i) {
            int chunk = tid * 2 + i;
            int m = chunk >> 2, c = chunk & 3;
            const void* g = Ab + (size_t)(row0 + m) * Kd + k0 + c * 8;
            cp_async16(ab + (uint32_t)(m * GLDA + c * 8) * 2, g);
        }
        #pragma unroll
        for (int i = 0; i < 2; ++i) {
            int chunk = tid * 2 + i;
            int k = chunk >> 4, c = chunk & 15;
            const void* g = Bf + (size_t)(k0 + k) * Nd + col0 + c * 8;
            cp_async16(bb + (uint32_t)(k * GLDB + c * 8) * 2, g);
        }
    };

    #pragma unroll
    for (int p = 0; p < GSTAGES - 1; ++p) {
        if (p < KT) load_tile(p, p);
        cp_commit();
    }

    for (int kt = 0; kt < KT; ++kt) {
        cp_wait<GSTAGES - 2>();
        __syncthreads();
        int buf = kt & (GSTAGES - 1);
        uint32_t ab = as0 + buf * GABYTES;
        uint32_t bb = bs0 + buf * GBBYTES;

        #pragma unroll
        for (int kk = 0; kk < 2; ++kk) {
            uint32_t af[2][4];
            #pragma unroll
            for (int mi = 0; mi < 2; ++mi) {
                int m  = wm * 32 + mi * 16 + (lane & 15);
                int kc = kk * 16 + (lane >> 4) * 8;
                ldm_x4(af[mi], ab + (uint32_t)(m * GLDA + kc) * 2);
            }
            uint32_t bfrag[8][2];
            #pragma unroll
            for (int ni4 = 0; ni4 < 4; ++ni4) {
                int g    = lane >> 3;
                int krow = kk * 16 + (g & 1) * 8 + (lane & 7);
                int ncol = wn * 64 + ni4 * 16 + (g >> 1) * 8;
                uint32_t r[4];
                ldm_x4_trans(r, bb + (uint32_t)(krow * GLDB + ncol) * 2);
                bfrag[2 * ni4][0] = r[0]; bfrag[2 * ni4][1] = r[1];
                bfrag[2 * ni4 + 1][0] = r[2]; bfrag[2 * ni4 + 1][1] = r[3];
            }
            #pragma unroll
            for (int mi = 0; mi < 2; ++mi)
                #pragma unroll
                for (int ni = 0; ni < 8; ++ni)
                    mma_f16(acc[mi][ni], af[mi], bfrag[ni]);
        }

        int nx = kt + GSTAGES - 1;
        if (nx < KT) load_tile(nx & (GSTAGES - 1), nx);
        cp_commit();
    }

    // epilogue
    #pragma unroll
    for (int mi = 0; mi < 2; ++mi) {
        int r = row0 + wm * 32 + mi * 16 + (lane >> 2);
        #pragma unroll
        for (int ni = 0; ni < 8; ++ni) {
            int c = col0 + wn * 64 + ni * 8 + (lane & 3) * 2;
            float b0 = 0.f, b1 = 0.f;
            if (BIAS) { b0 = bias[c]; b1 = bias[c + 1]; }
            #pragma unroll
            for (int half = 0; half < 2; ++half) {
                int rr = r + half * 8;
                float v0 = acc[mi][ni][half * 2 + 0] + b0;
                float v1 = acc[mi][ni][half * 2 + 1] + b1;
                if (GELU) {
                    v0 = 0.5f * v0 * (1.f + erff(v0 * 0.70710678118654752f));
                    v1 = 0.5f * v1 * (1.f + erff(v1 * 0.70710678118654752f));
                }
                if (RES) {
                    const float2 rv = *(const float2*)(res + (size_t)rr * Nd + c);
                    v0 += rv.x; v1 += rv.y;
                }
                if (OUT == 0) {
                    *(float2*)(Cf + (size_t)rr * Nd + c) = make_float2(v0, v1);
                } else if (OUT == 3) {
                    split_write2_h(v0, v1, Chh + (size_t)rr * Nd + c, Chl + (size_t)rr * Nd + c);
                } else {   // OUT == 4
                    __half2 hv = __halves2half2(__float2half_rn(v0), __float2half_rn(v1));
                    *(__half2*)(Chh + (size_t)rr * Nd + c) = hv;
                }
            }
        }
    }
}

// ---------------- flash attention (fp16 2-term Q, 64-row Q tiles) ----------------
// qkvh/qkvl: [M, 2304] fp16 planes.  Q exact as (Qh,Ql); K,V single-rounded (hi).
// S = Qh K^T + Ql K^T; O += Ph V + Pl V.
#define LDQ 72
#define FA_TILE (64 * LDQ)
#define FA_SMEM (4 * FA_TILE * 2)   // 36864 B
__global__ void __launch_bounds__(128)
flash_kernel(const __half* __restrict__ qkvh,
             const __half* __restrict__ qkvl,
             __half* __restrict__ oh, __half* __restrict__ ol)
{
    extern __shared__ __half fsm[];
    __half* Qh = fsm;
    __half* Ql = Qh + FA_TILE;
    __half* Kh = Ql + FA_TILE;
    __half* Vh = Kh + FA_TILE;

    int it = (S_ / 64 - 1) - blockIdx.x;   // heavy causal tiles first
    int z  = blockIdx.y;
    int b = z / H_, h = z % H_;
    int tid = threadIdx.x, lane = tid & 31, wm = tid >> 5;
    size_t rowbase = (size_t)b * S_;

    {
        size_t qoff = (rowbase + it * 64) * QKVN + h * D_;
        for (int cc = tid; cc < 512; cc += 128) {
            int r = cc >> 3, c = cc & 7;
            *(uint4*)&Qh[r * LDQ + c * 8] = *(const uint4*)(qkvh + qoff + (size_t)r * QKVN + c * 8);
            *(uint4*)&Ql[r * LDQ + c * 8] = *(const uint4*)(qkvl + qoff + (size_t)r * QKVN + c * 8);
        }
    }
    uint32_t qh_s = (uint32_t)__cvta_generic_to_shared(Qh);
    uint32_t ql_s = (uint32_t)__cvta_generic_to_shared(Ql);
    uint32_t kh_s = (uint32_t)__cvta_generic_to_shared(Kh);
    uint32_t vh_s = (uint32_t)__cvta_generic_to_shared(Vh);

    float oacc[8][4];
    #pragma unroll
    for (int j = 0; j < 8; ++j)
        #pragma unroll
        for (int t = 0; t < 4; ++t) oacc[j][t] = 0.f;
    float m_prev[2] = { -1e30f, -1e30f };
    float lsum[2]   = { 0.f, 0.f };

    for (int jt = 0; jt <= it; ++jt) {
        __syncthreads();
        size_t koff = (rowbase + jt * 64) * QKVN + E_ + h * D_;
        size_t voff = koff + E_;
        for (int cc = tid; cc < 512; cc += 128) {
            int r = cc >> 3, c = cc & 7;
            size_t gr = (size_t)r * QKVN + c * 8;
            int so = r * LDQ + c * 8;
            *(uint4*)&Kh[so] = *(const uint4*)(qkvh + koff + gr);
            *(uint4*)&Vh[so] = *(const uint4*)(qkvh + voff + gr);
        }
        __syncthreads();

        float sacc[8][4];
        #pragma unroll
        for (int j = 0; j < 8; ++j)
            #pragma unroll
            for (int t = 0; t < 4; ++t) sacc[j][t] = 0.f;

        // S = Qh K + Ql K
        #pragma unroll
        for (int kc = 0; kc < 4; ++kc) {
            uint32_t a_off = (uint32_t)((wm * 16 + (lane & 15)) * LDQ + kc * 16 + (lane >> 4) * 8) * 2;
            uint32_t afh[4], afl[4];
            ldm_x4(afh, qh_s + a_off);
            ldm_x4(afl, ql_s + a_off);
            #pragma unroll
            for (int np = 0; np < 4; ++np) {
                int nrow = np * 16 + (lane & 7) + ((lane >> 4) << 3);
                int ncol = kc * 16 + ((lane >> 3) & 1) * 8;
                uint32_t b_off = (uint32_t)(nrow * LDQ + ncol) * 2;
                uint32_t brh[4];
                ldm_x4(brh, kh_s + b_off);
                mma_f16(sacc[np * 2],     afh, brh);
                mma_f16(sacc[np * 2],     afl, brh);
                mma_f16(sacc[np * 2 + 1], afh, brh + 2);
                mma_f16(sacc[np * 2 + 1], afl, brh + 2);
            }
        }

        int rloc = wm * 16 + (lane >> 2);
        float mtile[2] = { -1e30f, -1e30f };
        bool diag = (jt == it);
        #pragma unroll
        for (int j = 0; j < 8; ++j) {
            int cg = jt * 64 + j * 8 + (lane & 3) * 2;
            #pragma unroll
            for (int rh = 0; rh < 2; ++rh) {
                int rg = it * 64 + rloc + rh * 8;
                float s0 = sacc[j][rh * 2]     * 0.125f;
                float s1 = sacc[j][rh * 2 + 1] * 0.125f;
                if (diag) {
                    if (cg     > rg) s0 = -1e30f;
                    if (cg + 1 > rg) s1 = -1e30f;
                }
                sacc[j][rh * 2]     = s0;
                sacc[j][rh * 2 + 1] = s1;
                mtile[rh] = fmaxf(mtile[rh], fmaxf(s0, s1));
            }
        }
        #pragma unroll
        for (int rh = 0; rh < 2; ++rh) {
            mtile[rh] = fmaxf(mtile[rh], __shfl_xor_sync(0xffffffff, mtile[rh], 1));
            mtile[rh] = fmaxf(mtile[rh], __shfl_xor_sync(0xffffffff, mtile[rh], 2));
        }
        float alpha[2];
        #pragma unroll
        for (int rh = 0; rh < 2; ++rh) {
            float mn = fmaxf(m_prev[rh], mtile[rh]);
            alpha[rh] = __expf(m_prev[rh] - mn);
            m_prev[rh] = mn;
        }
        float rsum[2] = { 0.f, 0.f };
        #pragma unroll
        for (int j = 0; j < 8; ++j)
            #pragma unroll
            for (int rh = 0; rh < 2; ++rh) {
                float p0 = __expf(sacc[j][rh * 2]     - m_prev[rh]);
                float p1 = __expf(sacc[j][rh * 2 + 1] - m_prev[rh]);
                sacc[j][rh * 2] = p0; sacc[j][rh * 2 + 1] = p1;
                rsum[rh] += p0 + p1;
            }
        #pragma unroll
        for (int rh = 0; rh < 2; ++rh) {
            rsum[rh] += __shfl_xor_sync(0xffffffff, rsum[rh], 1);
            rsum[rh] += __shfl_xor_sync(0xffffffff, rsum[rh], 2);
            lsum[rh] = lsum[rh] * alpha[rh] + rsum[rh];
        }
        #pragma unroll
        for (int j = 0; j < 8; ++j)
            #pragma unroll
            for (int rh = 0; rh < 2; ++rh) {
                oacc[j][rh * 2]     *= alpha[rh];
                oacc[j][rh * 2 + 1] *= alpha[rh];
            }
        // O += Ph V + Pl V
        #pragma unroll
        for (int kc = 0; kc < 4; ++kc) {
            uint32_t pah[4], pal[4];
            split_pack2_h(sacc[2 * kc][0],     sacc[2 * kc][1],     pah[0], pal[0]);
            split_pack2_h(sacc[2 * kc][2],     sacc[2 * kc][3],     pah[1], pal[1]);
            split_pack2_h(sacc[2 * kc + 1][0], sacc[2 * kc + 1][1], pah[2], pal[2]);
            split_pack2_h(sacc[2 * kc + 1][2], sacc[2 * kc + 1][3], pah[3], pal[3]);
            #pragma unroll
            for (int np = 0; np < 4; ++np) {
                int g = lane >> 3;
                int krow = kc * 16 + (g & 1) * 8 + (lane & 7);
                int ncol = np * 16 + (g >> 1) * 8;
                uint32_t v_off = (uint32_t)(krow * LDQ + ncol) * 2;
                uint32_t brh[4];
                ldm_x4_trans(brh, vh_s + v_off);
                mma_f16(oacc[np * 2],     pah, brh);
                mma_f16(oacc[np * 2],     pal, brh);
                mma_f16(oacc[np * 2 + 1], pah, brh + 2);
                mma_f16(oacc[np * 2 + 1], pal, brh + 2);
            }
        }
    }

    float inv[2] = { 1.f / lsum[0], 1.f / lsum[1] };
    size_t gr0 = rowbase + it * 64 + wm * 16 + (lane >> 2);
    #pragma unroll
    for (int j = 0; j < 8; ++j) {
        int col = h * D_ + j * 8 + (lane & 3) * 2;
        #pragma unroll
        for (int rh = 0; rh < 2; ++rh) {
            size_t gr = gr0 + rh * 8;
            float v0 = oacc[j][rh * 2]     * inv[rh];
            float v1 = oacc[j][rh * 2 + 1] * inv[rh];
            split_write2_h(v0, v1, oh + gr * E_ + col, ol + gr * E_ + col);
        }
    }
}

// ---------------- host launcher ----------------
extern "C" void kernel_launch(void* const* d_in, const int* in_sizes, int n_in,
                              void* d_out, int out_size)
{
    const int*   tokens  = (const int*)  d_in[0];
    const float* tok_emb = (const float*)d_in[1];
    const float* pos_emb = (const float*)d_in[2];
    const float* Wq = (const float*)d_in[3];
    const float* bq = (const float*)d_in[4];
    const float* Wk = (const float*)d_in[5];
    const float* bk = (const float*)d_in[6];
    const float* Wv = (const float*)d_in[7];
    const float* bv = (const float*)d_in[8];
    const float* Wo = (const float*)d_in[9];
    const float* bo = (const float*)d_in[10];
    const float* ln1_g = (const float*)d_in[11];
    const float* ln1_b = (const float*)d_in[12];
    const float* ln2_g = (const float*)d_in[13];
    const float* ln2_b = (const float*)d_in[14];
    const float* W1 = (const float*)d_in[15];
    const float* b1 = (const float*)d_in[16];
    const float* W2 = (const float*)d_in[17];
    const float* b2 = (const float*)d_in[18];
    const float* lnf_g = (const float*)d_in[19];
    const float* lnf_b = (const float*)d_in[20];
    const float* Wf = (const float*)d_in[21];
    const float* bf = (const float*)d_in[22];
    float* out = (float*)d_out;

    float *x, *bqkv;
    __half *qkvh, *qkvl;
    __half *ahE, *alE, *ahF;
    __half *wqkv, *wo, *w1, *w2, *wf;
    cudaGetSymbolAddress((void**)&x,    g_x);
    cudaGetSymbolAddress((void**)&bqkv, g_bqkv);
    cudaGetSymbolAddress((void**)&qkvh, g_qkvh);
    cudaGetSymbolAddress((void**)&qkvl, g_qkvl);
    cudaGetSymbolAddress((void**)&ahE,  g_ahE);
    cudaGetSymbolAddress((void**)&alE,  g_alE);
    cudaGetSymbolAddress((void**)&ahF,  g_ahF);
    cudaGetSymbolAddress((void**)&wqkv, g_wqkv);
    cudaGetSymbolAddress((void**)&wo,   g_wo);
    cudaGetSymbolAddress((void**)&w1,   g_w1);
    cudaGetSymbolAddress((void**)&w2,   g_w2);
    cudaGetSymbolAddress((void**)&wf,   g_wf);

    const size_t EE = (size_t)E_ * E_;
    cudaFuncSetAttribute(flash_kernel, cudaFuncAttributeMaxDynamicSharedMemorySize, FA_SMEM);
    cudaFuncSetAttribute(bgemm2_kernel<1, 3, true, false, false>,
                         cudaFuncAttributeMaxDynamicSharedMemorySize, GSMEM);
    cudaFuncSetAttribute(bgemm2_kernel<2, 0, true, true, false>,
                         cudaFuncAttributeMaxDynamicSharedMemorySize, GSMEM);
    cudaFuncSetAttribute(bgemm2_kernel<1, 4, true, false, true>,
                         cudaFuncAttributeMaxDynamicSharedMemorySize, GSMEM);
    cudaFuncSetAttribute(bgemm2_kernel<1, 0, true, true, false>,
                         cudaFuncAttributeMaxDynamicSharedMemorySize, GSMEM);
    cudaFuncSetAttribute(bgemm2_kernel<1, 0, true, false, false>,
                         cudaFuncAttributeMaxDynamicSharedMemorySize, GSMEM);

    // ---- fused weight conversion (one launch) ----
    convert_all_kernel<<<4096, 256>>>(
        (const float4*)Wq, (const float4*)Wk, (const float4*)Wv, (const float4*)Wo,
        (const float4*)W1, (const float4*)W2, (const float4*)Wf,
        (uint2*)wqkv, (uint2*)wo, (uint2*)w1, (uint2*)w2, (uint2*)wf);
    concat_bias_kernel<<<(L_ * QKVN + 255) / 256, 256>>>(bq, bk, bv, bqkv);

    embed_kernel<<<M_, 192>>>(tokens, tok_emb, pos_emb, x);

    dim3 gQKV (M_ / 128, QKVN / 128);   // 16 x 18
    dim3 gProj(M_ / 128, E_ / 128);     // 16 x 6
    dim3 gFF1 (M_ / 128, FF_ / 128);    // 16 x 36
    dim3 gHead(M_ / 128, V_ / 128);     // 16 x 250
    dim3 gFA  (S_ / 64, B_ * H_);       // 16 x 24

    for (int l = 0; l < L_; ++l) {
        size_t qoff = (size_t)l * E_ * QKVN;
        size_t ooff = (size_t)l * EE;
        size_t f1 = (size_t)l * E_ * FF_;
        size_t f2 = (size_t)l * FF_ * E_;

        // LN1 -> single fp16 plane
        ln_h_kernel<<<M_, 256>>>(x, ln1_g + l * E_, ln1_b + l * E_, ahE);

        // qkv = h @ Wqkv + b   (1-term input, split-plane output for flash Q)
        bgemm2_kernel<1, 3, true, false, false><<<gQKV, 256, GSMEM>>>(
            ahE, ahE, wqkv + qoff, bqkv + l * QKVN, nullptr,
            nullptr, qkvh, qkvl, QKVN, E_);

        flash_kernel<<<gFA, 128, FA_SMEM>>>(qkvh, qkvl, ahE, alE);

        // x = x + o @ Wo + bo   (2-term: attention output kept exact)
        bgemm2_kernel<2, 0, true, true, false><<<gProj, 256, GSMEM>>>(
            ahE, alE, wo + ooff, bo + l * E_, x,
            x, nullptr, nullptr, E_, E_);

        // LN2 -> single fp16 plane
        ln_h_kernel<<<M_, 256>>>(x, ln2_g + l * E_, ln2_b + l * E_, ahE);

        // ff = gelu(h @ W1 + b1)  (1-term input, single fp16 output)
        bgemm2_kernel<1, 4, true, false, true><<<gFF1, 256, GSMEM>>>(
            ahE, ahE, w1 + f1, b1 + l * FF_, nullptr,
            nullptr, ahF, nullptr, FF_, E_);

        // x = x + ff @ W2 + b2   (1-term)
        bgemm2_kernel<1, 0, true, true, false><<<gProj, 256, GSMEM>>>(
            ahF, ahF, w2 + f2, b2 + l * E_, x,
            x, nullptr, nullptr, E_, FF_);
    }

    ln_h_kernel<<<M_, 256>>>(x, lnf_g, lnf_b, ahE);
    // LM head: single-term fp16
    bgemm2_kernel<1, 0, true, false, false><<<gHead, 256, GSMEM>>>(
        ahE, ahE, wf, bf, nullptr,
        out, nullptr, nullptr, V_, E_);
}